// round 1
// baseline (speedup 1.0000x reference)
#include <cuda_runtime.h>
#include <math.h>

#define NH     8
#define BATCH  4
#define SEQ    1024
#define DMODEL 512
#define DH     64

// ---- scratch (device globals; no allocation allowed) ----
__device__ float gQ[BATCH * NH * SEQ * DH];     // 8 MB, pre-scaled by 1/sqrt(d)
__device__ float gK[BATCH * NH * SEQ * DH];     // 8 MB
__device__ float gV[BATCH * NH * SEQ * DH];     // 8 MB
__device__ float gVW[BATCH * NH * SEQ];         // 128 KB
__device__ float gS[(size_t)BATCH * NH * SEQ * SEQ]; // 128 MB scores(+mask)

// ============================================================
// K1: qkv = emb(4096x512) @ W(512x1536) + bias, scatter to Q/K/V
//     in (b,h,n,dh) layout; Q scaled by 1/sqrt(512).
// 128x128 block tile, BK=16, 8x8 per thread, 256 threads.
// ============================================================
__global__ __launch_bounds__(256) void qkv_gemm(
    const float* __restrict__ A,     // emb  (4096,512)
    const float* __restrict__ B,     // W    (512,1536)
    const float* __restrict__ bias)  // (1536,)
{
    const int N = 1536, KD = 512;
    __shared__ float As[16][128];   // transposed A tile
    __shared__ float Bs[16][128];

    const int bx = blockIdx.x;      // N tile (0..11)
    const int by = blockIdx.y;      // M tile (0..31)
    const int tid = threadIdx.x;
    const int tx = tid & 15;        // 0..15 (N dir)
    const int ty = tid >> 4;        // 0..15 (M dir)

    float acc[8][8];
    #pragma unroll
    for (int m = 0; m < 8; m++)
        #pragma unroll
        for (int n = 0; n < 8; n++) acc[m][n] = 0.f;

    for (int k0 = 0; k0 < KD; k0 += 16) {
        // A tile: 128 rows x 16 cols = 512 float4
        #pragma unroll
        for (int l = 0; l < 2; l++) {
            int f = tid + l * 256;
            int r = f >> 2, c4 = f & 3;
            float4 v = *(const float4*)(A + (size_t)(by * 128 + r) * KD + k0 + c4 * 4);
            As[c4 * 4 + 0][r] = v.x;
            As[c4 * 4 + 1][r] = v.y;
            As[c4 * 4 + 2][r] = v.z;
            As[c4 * 4 + 3][r] = v.w;
        }
        // B tile: 16 rows x 128 cols = 512 float4
        #pragma unroll
        for (int l = 0; l < 2; l++) {
            int f = tid + l * 256;
            int r = f >> 5, c4 = f & 31;
            float4 v = *(const float4*)(B + (size_t)(k0 + r) * N + bx * 128 + c4 * 4);
            *(float4*)&Bs[r][c4 * 4] = v;
        }
        __syncthreads();

        #pragma unroll
        for (int k = 0; k < 16; k++) {
            float4 a0 = *(float4*)&As[k][ty * 8];
            float4 a1 = *(float4*)&As[k][ty * 8 + 4];
            float4 b0 = *(float4*)&Bs[k][tx * 8];
            float4 b1 = *(float4*)&Bs[k][tx * 8 + 4];
            float av[8] = {a0.x, a0.y, a0.z, a0.w, a1.x, a1.y, a1.z, a1.w};
            float bv[8] = {b0.x, b0.y, b0.z, b0.w, b1.x, b1.y, b1.z, b1.w};
            #pragma unroll
            for (int m = 0; m < 8; m++)
                #pragma unroll
                for (int n = 0; n < 8; n++)
                    acc[m][n] = fmaf(av[m], bv[n], acc[m][n]);
        }
        __syncthreads();
    }

    const float scaleQ = 1.0f / sqrtf((float)DMODEL);
    // Whole 128-col block lives in one of {q,k,v} (1536/128 aligned to 512).
    const int colBase = bx * 128 + tx * 8;
    const int which = colBase / DMODEL;          // 0=q,1=k,2=v
    const int idx0  = colBase % DMODEL;
    const int hh    = idx0 >> 6;                 // constant over n (tx*8 stays in one head)
    const int w0    = idx0 & 63;

    #pragma unroll
    for (int m = 0; m < 8; m++) {
        int row = by * 128 + ty * 8 + m;
        int b = row >> 10, i = row & 1023;
        size_t dstBase = ((size_t)((b * NH + hh) * SEQ + i)) * DH + w0;
        #pragma unroll
        for (int n = 0; n < 8; n++) {
            float c = acc[m][n] + bias[colBase + n];
            if (which == 0)      gQ[dstBase + n] = c * scaleQ;
            else if (which == 1) gK[dstBase + n] = c;
            else                 gV[dstBase + n] = c;
        }
    }
}

// ============================================================
// K2: vw[b,h,j] = sum_w V[b,h,j,w] * w_force[h*64+w]
// one warp per (b,h,j) row; 8 rows per block.
// ============================================================
__global__ __launch_bounds__(256) void vw_kernel(const float* __restrict__ wf)
{
    int warp = threadIdx.x >> 5;
    int lane = threadIdx.x & 31;
    int row = blockIdx.x * 8 + warp;             // 0..32767
    int h = (row >> 10) & 7;
    const float* vrow = gV + (size_t)row * DH;
    float s = vrow[lane] * wf[h * 64 + lane] + vrow[lane + 32] * wf[h * 64 + lane + 32];
    #pragma unroll
    for (int o = 16; o; o >>= 1) s += __shfl_xor_sync(0xffffffffu, s, o);
    if (lane == 0) gVW[row] = s;
}

// ============================================================
// K3: per (b,h): S = Q(1024x64) @ K(1024x64)^T + d_mask
// 128x128 tile, BK=16 (4 iters), 8x8 per thread.
// ============================================================
__global__ __launch_bounds__(256) void scores_gemm(const float* __restrict__ dmask)
{
    __shared__ float As[16][128];
    __shared__ float Bs[16][128];

    const int bh = blockIdx.z;
    const int j0 = blockIdx.x * 128;
    const int i0 = blockIdx.y * 128;
    const int tid = threadIdx.x;
    const int tx = tid & 15, ty = tid >> 4;

    const float* Qb = gQ + (size_t)bh * SEQ * DH;
    const float* Kb = gK + (size_t)bh * SEQ * DH;

    float acc[8][8];
    #pragma unroll
    for (int m = 0; m < 8; m++)
        #pragma unroll
        for (int n = 0; n < 8; n++) acc[m][n] = 0.f;

    for (int k0 = 0; k0 < DH; k0 += 16) {
        #pragma unroll
        for (int l = 0; l < 2; l++) {
            int f = tid + l * 256;
            int r = f >> 2, c4 = f & 3;
            float4 v = *(const float4*)(Qb + (size_t)(i0 + r) * DH + k0 + c4 * 4);
            As[c4 * 4 + 0][r] = v.x;
            As[c4 * 4 + 1][r] = v.y;
            As[c4 * 4 + 2][r] = v.z;
            As[c4 * 4 + 3][r] = v.w;
        }
        #pragma unroll
        for (int l = 0; l < 2; l++) {
            int f = tid + l * 256;
            int r = f >> 2, c4 = f & 3;           // r = j within tile
            float4 v = *(const float4*)(Kb + (size_t)(j0 + r) * DH + k0 + c4 * 4);
            Bs[c4 * 4 + 0][r] = v.x;
            Bs[c4 * 4 + 1][r] = v.y;
            Bs[c4 * 4 + 2][r] = v.z;
            Bs[c4 * 4 + 3][r] = v.w;
        }
        __syncthreads();

        #pragma unroll
        for (int k = 0; k < 16; k++) {
            float4 a0 = *(float4*)&As[k][ty * 8];
            float4 a1 = *(float4*)&As[k][ty * 8 + 4];
            float4 b0 = *(float4*)&Bs[k][tx * 8];
            float4 b1 = *(float4*)&Bs[k][tx * 8 + 4];
            float av[8] = {a0.x, a0.y, a0.z, a0.w, a1.x, a1.y, a1.z, a1.w};
            float bv[8] = {b0.x, b0.y, b0.z, b0.w, b1.x, b1.y, b1.z, b1.w};
            #pragma unroll
            for (int m = 0; m < 8; m++)
                #pragma unroll
                for (int n = 0; n < 8; n++)
                    acc[m][n] = fmaf(av[m], bv[n], acc[m][n]);
        }
        __syncthreads();
    }

    // epilogue: add mask, store scores (vectorized)
    #pragma unroll
    for (int m = 0; m < 8; m++) {
        size_t rowBase = ((size_t)bh * SEQ + (i0 + ty * 8 + m)) * SEQ + j0 + tx * 8;
        float4 d0 = *(const float4*)(dmask + rowBase);
        float4 d1 = *(const float4*)(dmask + rowBase + 4);
        float4 s0 = make_float4(acc[m][0] + d0.x, acc[m][1] + d0.y,
                                acc[m][2] + d0.z, acc[m][3] + d0.w);
        float4 s1 = make_float4(acc[m][4] + d1.x, acc[m][5] + d1.y,
                                acc[m][6] + d1.z, acc[m][7] + d1.w);
        *(float4*)(gS + rowBase)     = s0;
        *(float4*)(gS + rowBase + 4) = s1;
    }
}

// ============================================================
// K4: per (b,i): for each h softmax the score row, fold vw,
//     then contract with dirs -> out[b,i,0..2].
// 256 threads, thread t owns j = t, t+256, t+512, t+768.
// ============================================================
__device__ __forceinline__ float warpMax(float v) {
    #pragma unroll
    for (int o = 16; o; o >>= 1) v = fmaxf(v, __shfl_xor_sync(0xffffffffu, v, o));
    return v;
}
__device__ __forceinline__ float warpSum(float v) {
    #pragma unroll
    for (int o = 16; o; o >>= 1) v += __shfl_xor_sync(0xffffffffu, v, o);
    return v;
}

__global__ __launch_bounds__(256) void out_kernel(
    const float* __restrict__ dirs,   // (b, n, n, 3)
    const float* __restrict__ bf,     // (1,)
    float* __restrict__ out)          // (b, n, 3)
{
    __shared__ float redm[8];
    __shared__ float reds[8];
    __shared__ float redo[3][8];

    const int bi = blockIdx.x;        // 0..4095
    const int b = bi >> 10, i = bi & 1023;
    const int tid = threadIdx.x;
    const int lane = tid & 31, warp = tid >> 5;

    float sacc[4] = {0.f, 0.f, 0.f, 0.f};

    for (int h = 0; h < NH; h++) {
        const int bh = b * NH + h;
        const float* srow = gS + ((size_t)bh * SEQ + i) * SEQ;
        const float* vwp  = gVW + (size_t)bh * SEQ;

        float e[4];
        float m = -1e30f;
        #pragma unroll
        for (int l = 0; l < 4; l++) {
            e[l] = srow[tid + l * 256];
            m = fmaxf(m, e[l]);
        }
        m = warpMax(m);
        if (lane == 0) redm[warp] = m;
        __syncthreads();
        float gm = redm[0];
        #pragma unroll
        for (int w = 1; w < 8; w++) gm = fmaxf(gm, redm[w]);

        float psum = 0.f;
        #pragma unroll
        for (int l = 0; l < 4; l++) {
            e[l] = __expf(e[l] - gm);
            psum += e[l];
        }
        psum = warpSum(psum);
        if (lane == 0) reds[warp] = psum;
        __syncthreads();
        float gsum = reds[0];
        #pragma unroll
        for (int w = 1; w < 8; w++) gsum += reds[w];
        float inv = 1.0f / gsum;

        #pragma unroll
        for (int l = 0; l < 4; l++)
            sacc[l] += e[l] * inv * vwp[tid + l * 256];
        __syncthreads();   // protect redm/reds for next h
    }

    // contract with dirs
    float o0 = 0.f, o1 = 0.f, o2 = 0.f;
    const float* dp = dirs + ((size_t)(b * SEQ + i)) * SEQ * 3;
    #pragma unroll
    for (int l = 0; l < 4; l++) {
        int j = tid + l * 256;
        float s = sacc[l];
        o0 = fmaf(s, dp[j * 3 + 0], o0);
        o1 = fmaf(s, dp[j * 3 + 1], o1);
        o2 = fmaf(s, dp[j * 3 + 2], o2);
    }
    o0 = warpSum(o0); o1 = warpSum(o1); o2 = warpSum(o2);
    if (lane == 0) { redo[0][warp] = o0; redo[1][warp] = o1; redo[2][warp] = o2; }
    __syncthreads();
    if (tid < 3) {
        float r = 0.f;
        #pragma unroll
        for (int w = 0; w < 8; w++) r += redo[tid][w];
        out[(size_t)bi * 3 + tid] = r + bf[0];
    }
}

// ============================================================
extern "C" void kernel_launch(void* const* d_in, const int* in_sizes, int n_in,
                              void* d_out, int out_size)
{
    const float* emb   = (const float*)d_in[0];  // (4,1024,512)
    const float* dirs  = (const float*)d_in[1];  // (4,1024,1024,3)
    const float* dmask = (const float*)d_in[2];  // (32,1024,1024)
    const float* Wp    = (const float*)d_in[3];  // (512,1536)
    const float* bp    = (const float*)d_in[4];  // (1536,)
    const float* wf    = (const float*)d_in[5];  // (512,)
    const float* bf    = (const float*)d_in[6];  // (1,)
    float* out = (float*)d_out;                  // (4,1024,3)

    qkv_gemm<<<dim3(12, 32), 256>>>(emb, Wp, bp);
    vw_kernel<<<BATCH * NH * SEQ / 8, 256>>>(wf);
    scores_gemm<<<dim3(8, 8, BATCH * NH), 256>>>(dmask);
    out_kernel<<<BATCH * SEQ, 256>>>(dirs, bf, out);
}

// round 3
// speedup vs baseline: 1.3035x; 1.3035x over previous
#include <cuda_runtime.h>
#include <cuda_bf16.h>
#include <stdint.h>
#include <math.h>

#define NH     8
#define BATCH  4
#define SEQ    1024
#define DMODEL 512
#define DH     64
#define SCALEQ 0.04419417382415922f  // 1/sqrt(512)

// ---- scratch (device globals; no allocation allowed) ----
__device__ float gQ[BATCH * NH * SEQ * DH];          // pre-scaled by 1/sqrt(d)
__device__ float gK[BATCH * NH * SEQ * DH];
__device__ float gV[BATCH * NH * SEQ * DH];
__device__ float gVW[BATCH * NH * SEQ];
__device__ float gS[(size_t)BATCH * NH * SEQ * SEQ]; // 128 MB scores(+mask)

// ============================================================
// bf16 helpers
// ============================================================
__device__ __forceinline__ uint32_t pack_bf16x2(float x, float y) {
    __nv_bfloat162 t;
    t.x = __float2bfloat16(x);
    t.y = __float2bfloat16(y);
    return *(uint32_t*)&t;
}
__device__ __forceinline__ void split_bf16(float x, __nv_bfloat16& h, __nv_bfloat16& l) {
    h = __float2bfloat16(x);
    l = __float2bfloat16(x - __bfloat162float(h));
}

__device__ __forceinline__ void mma_bf16(float c[4], uint32_t a0, uint32_t a1,
                                         uint32_t a2, uint32_t a3,
                                         uint32_t b0, uint32_t b1) {
    asm volatile(
        "mma.sync.aligned.m16n8k16.row.col.f32.bf16.bf16.f32 "
        "{%0,%1,%2,%3}, {%4,%5,%6,%7}, {%8,%9}, {%0,%1,%2,%3};"
        : "+f"(c[0]), "+f"(c[1]), "+f"(c[2]), "+f"(c[3])
        : "r"(a0), "r"(a1), "r"(a2), "r"(a3), "r"(b0), "r"(b1));
}

// SMEM tile stride: 40 bf16 elements (80B) -> conflict-free fragment loads
#define TS 40

// One (hi/lo selected) pass over a BK=32 chunk.
// A: [128][TS] bf16 (row-major, k contiguous). B: [128][TS] bf16 ([n][k]).
__device__ __forceinline__ void mma_pass(
    const __nv_bfloat16* __restrict__ A, const __nv_bfloat16* __restrict__ B,
    float c[2][8][4], int wM, int wN, int lane)
{
    const int r  = lane >> 2;
    const int cq = (lane & 3) * 2;
#pragma unroll
    for (int ks = 0; ks < 2; ks++) {
        const int k0 = ks * 16;
        uint32_t a[2][4];
#pragma unroll
        for (int mt = 0; mt < 2; mt++) {
            const int rb = wM * 32 + mt * 16 + r;
            a[mt][0] = *(const uint32_t*)(A + rb * TS + k0 + cq);
            a[mt][1] = *(const uint32_t*)(A + (rb + 8) * TS + k0 + cq);
            a[mt][2] = *(const uint32_t*)(A + rb * TS + k0 + cq + 8);
            a[mt][3] = *(const uint32_t*)(A + (rb + 8) * TS + k0 + cq + 8);
        }
#pragma unroll
        for (int nt = 0; nt < 8; nt++) {
            const int nb = wN * 64 + nt * 8 + r;
            uint32_t b0 = *(const uint32_t*)(B + nb * TS + k0 + cq);
            uint32_t b1 = *(const uint32_t*)(B + nb * TS + k0 + cq + 8);
#pragma unroll
            for (int mt = 0; mt < 2; mt++)
                mma_bf16(c[mt][nt], a[mt][0], a[mt][1], a[mt][2], a[mt][3], b0, b1);
        }
    }
}

// Load 128x32 fp32 tile (row stride rs) into 4 float4 regs per thread.
__device__ __forceinline__ void load_rows_g(const float* __restrict__ src, int rs,
                                            int tid, float4 rg[4])
{
#pragma unroll
    for (int l = 0; l < 4; l++) {
        int idx = tid + l * 256;
        int row = idx >> 3, c4 = idx & 7;
        rg[l] = *(const float4*)(src + (size_t)row * rs + (c4 << 2));
    }
}
// Store the 128x32 regs into hi/lo bf16 SMEM tiles (k contiguous).
__device__ __forceinline__ void store_rows_s(__nv_bfloat16* hi, __nv_bfloat16* lo,
                                             int tid, const float4 rg[4])
{
#pragma unroll
    for (int l = 0; l < 4; l++) {
        int idx = tid + l * 256;
        int row = idx >> 3, c4 = idx & 7;
        int base = row * TS + (c4 << 2);
        float v[4] = {rg[l].x, rg[l].y, rg[l].z, rg[l].w};
        __nv_bfloat16 h[4], e[4];
#pragma unroll
        for (int j = 0; j < 4; j++) split_bf16(v[j], h[j], e[j]);
        *(uint32_t*)(hi + base)     = pack_bf16x2(v[0], v[1]) * 0 + (*(uint32_t*)&h[0] & 0xFFFF) + ((uint32_t)(*(uint16_t*)&h[1]) << 16);
        // (simpler explicit packs below)
        {
            __nv_bfloat162 t01, t23, u01, u23;
            t01.x = h[0]; t01.y = h[1]; t23.x = h[2]; t23.y = h[3];
            u01.x = e[0]; u01.y = e[1]; u23.x = e[2]; u23.y = e[3];
            *(__nv_bfloat162*)(hi + base)     = t01;
            *(__nv_bfloat162*)(hi + base + 2) = t23;
            *(__nv_bfloat162*)(lo + base)     = u01;
            *(__nv_bfloat162*)(lo + base + 2) = u23;
        }
    }
}

// ============================================================
// K1: qkv = emb(4096x512) @ W(512x1536) + bias, scatter to Q/K/V.
// 128x128 tile, BK=32, 16 chunks, bf16 split mma.
// ============================================================
__global__ __launch_bounds__(256) void qkv_mma(
    const float* __restrict__ A, const float* __restrict__ W,
    const float* __restrict__ bias)
{
    __shared__ __nv_bfloat16 Ah[128 * TS], Al[128 * TS];
    __shared__ __nv_bfloat16 Bh[128 * TS], Bl[128 * TS];
    __shared__ float bias_sm[128];

    const int tid = threadIdx.x;
    const int wid = tid >> 5, lane = tid & 31;
    const int wM = wid & 3, wN = wid >> 2;
    const int bx = blockIdx.x, by = blockIdx.y;

    if (tid < 128) bias_sm[tid] = bias[bx * 128 + tid];

    float c[2][8][4];
#pragma unroll
    for (int mt = 0; mt < 2; mt++)
#pragma unroll
        for (int nt = 0; nt < 8; nt++)
#pragma unroll
            for (int j = 0; j < 4; j++) c[mt][nt][j] = 0.f;

    const float* Abase = A + (size_t)(by * 128) * 512;
    float4 ra[4], rb[4];
    load_rows_g(Abase, 512, tid, ra);
    // B chunk 0: W rows 0..31, cols bx*128..; 4 float4/thread
#pragma unroll
    for (int l = 0; l < 4; l++) {
        int idx = tid + l * 256;
        int kr = idx >> 5, c4 = idx & 31;
        rb[l] = *(const float4*)(W + (size_t)kr * 1536 + bx * 128 + (c4 << 2));
    }

    for (int ch = 0; ch < 16; ch++) {
        store_rows_s(Ah, Al, tid, ra);
        // store B transposed: Bs[n][k]
#pragma unroll
        for (int l = 0; l < 4; l++) {
            int idx = tid + l * 256;
            int kr = idx >> 5, c4 = idx & 31;
            float v[4] = {rb[l].x, rb[l].y, rb[l].z, rb[l].w};
#pragma unroll
            for (int j = 0; j < 4; j++) {
                int n = (c4 << 2) + j;
                __nv_bfloat16 h, e;
                split_bf16(v[j], h, e);
                Bh[n * TS + kr] = h;
                Bl[n * TS + kr] = e;
            }
        }
        __syncthreads();

        if (ch < 15) {
            load_rows_g(Abase + (ch + 1) * 32, 512, tid, ra);
#pragma unroll
            for (int l = 0; l < 4; l++) {
                int idx = tid + l * 256;
                int kr = idx >> 5, c4 = idx & 31;
                rb[l] = *(const float4*)(W + (size_t)((ch + 1) * 32 + kr) * 1536
                                           + bx * 128 + (c4 << 2));
            }
        }

        mma_pass(Ah, Bh, c, wM, wN, lane);
        mma_pass(Ah, Bl, c, wM, wN, lane);
        mma_pass(Al, Bh, c, wM, wN, lane);
        __syncthreads();
    }

    // Epilogue: bias (+Q scale), scatter to gQ/gK/gV. float2 stores.
    const int r  = lane >> 2;
    const int cq = (lane & 3) * 2;
#pragma unroll
    for (int nt = 0; nt < 8; nt++) {
        const int lcol = wN * 64 + nt * 8 + cq;
        const int gcol = bx * 128 + lcol;
        const int which = gcol >> 9;
        const int idx = gcol & 511;
        const int h = idx >> 6, w = idx & 63;
        const float sc = (which == 0) ? SCALEQ : 1.0f;
        const float b0 = bias_sm[lcol], b1 = bias_sm[lcol + 1];
        float* p = (which == 0) ? gQ : (which == 1) ? gK : gV;
#pragma unroll
        for (int mt = 0; mt < 2; mt++) {
            const int grow = by * 128 + wM * 32 + mt * 16 + r;
            const int bb = grow >> 10, ii = grow & 1023;
            size_t dst = (((size_t)(bb * NH + h) * SEQ) + ii) * DH + w;
            float2 v0 = make_float2((c[mt][nt][0] + b0) * sc, (c[mt][nt][1] + b1) * sc);
            float2 v1 = make_float2((c[mt][nt][2] + b0) * sc, (c[mt][nt][3] + b1) * sc);
            *(float2*)(p + dst) = v0;
            *(float2*)(p + dst + (size_t)8 * DH) = v1;   // row +8
        }
    }
}

// ============================================================
// K2: vw[b,h,j] = sum_w V[b,h,j,w] * w_force[h*64+w]
// ============================================================
__global__ __launch_bounds__(256) void vw_kernel(const float* __restrict__ wf)
{
    int warp = threadIdx.x >> 5;
    int lane = threadIdx.x & 31;
    int row = blockIdx.x * 8 + warp;
    int h = (row >> 10) & 7;
    const float* vrow = gV + (size_t)row * DH;
    float s = vrow[lane] * wf[h * 64 + lane] + vrow[lane + 32] * wf[h * 64 + lane + 32];
#pragma unroll
    for (int o = 16; o; o >>= 1) s += __shfl_xor_sync(0xffffffffu, s, o);
    if (lane == 0) gVW[row] = s;
}

// ============================================================
// K3: per (b,h): S = Q(1024x64) @ K(1024x64)^T + d_mask, bf16 split mma.
// 128x128 tile, K=64 in 2 chunks of 32.
// ============================================================
__global__ __launch_bounds__(256) void scores_mma(const float* __restrict__ dmask)
{
    __shared__ __nv_bfloat16 Ah[128 * TS], Al[128 * TS];
    __shared__ __nv_bfloat16 Bh[128 * TS], Bl[128 * TS];

    const int tid = threadIdx.x;
    const int wid = tid >> 5, lane = tid & 31;
    const int wM = wid & 3, wN = wid >> 2;
    const int bh = blockIdx.z;
    const int j0 = blockIdx.x * 128;
    const int i0 = blockIdx.y * 128;

    const float* Qb = gQ + ((size_t)bh * SEQ + i0) * DH;
    const float* Kb = gK + ((size_t)bh * SEQ + j0) * DH;

    float c[2][8][4];
#pragma unroll
    for (int mt = 0; mt < 2; mt++)
#pragma unroll
        for (int nt = 0; nt < 8; nt++)
#pragma unroll
            for (int j = 0; j < 4; j++) c[mt][nt][j] = 0.f;

    float4 ra[4], rb[4];
    load_rows_g(Qb, DH, tid, ra);
    load_rows_g(Kb, DH, tid, rb);

#pragma unroll
    for (int ch = 0; ch < 2; ch++) {
        store_rows_s(Ah, Al, tid, ra);
        store_rows_s(Bh, Bl, tid, rb);
        __syncthreads();
        if (ch == 0) {
            load_rows_g(Qb + 32, DH, tid, ra);
            load_rows_g(Kb + 32, DH, tid, rb);
        }
        mma_pass(Ah, Bh, c, wM, wN, lane);
        mma_pass(Ah, Bl, c, wM, wN, lane);
        mma_pass(Al, Bh, c, wM, wN, lane);
        __syncthreads();
    }

    // Epilogue: add mask, store to gS (float2)
    const int r  = lane >> 2;
    const int cq = (lane & 3) * 2;
#pragma unroll
    for (int mt = 0; mt < 2; mt++) {
        const int i = i0 + wM * 32 + mt * 16 + r;
#pragma unroll
        for (int nt = 0; nt < 8; nt++) {
            const int j = j0 + wN * 64 + nt * 8 + cq;
            size_t addr0 = ((size_t)bh * SEQ + i) * SEQ + j;
            size_t addr1 = addr0 + (size_t)8 * SEQ;
            float2 m0 = *(const float2*)(dmask + addr0);
            float2 m1 = *(const float2*)(dmask + addr1);
            float2 v0 = make_float2(c[mt][nt][0] + m0.x, c[mt][nt][1] + m0.y);
            float2 v1 = make_float2(c[mt][nt][2] + m1.x, c[mt][nt][3] + m1.y);
            *(float2*)(gS + addr0) = v0;
            *(float2*)(gS + addr1) = v1;
        }
    }
}

// ============================================================
// K4: per (b,i): softmax rows, fold vw, contract with dirs.
// ============================================================
__device__ __forceinline__ float warpMax(float v) {
#pragma unroll
    for (int o = 16; o; o >>= 1) v = fmaxf(v, __shfl_xor_sync(0xffffffffu, v, o));
    return v;
}
__device__ __forceinline__ float warpSum(float v) {
#pragma unroll
    for (int o = 16; o; o >>= 1) v += __shfl_xor_sync(0xffffffffu, v, o);
    return v;
}

__global__ __launch_bounds__(256) void out_kernel(
    const float* __restrict__ dirs, const float* __restrict__ bf,
    float* __restrict__ out)
{
    __shared__ float redm[8];
    __shared__ float reds[8];
    __shared__ float redo[3][8];

    const int bi = blockIdx.x;
    const int b = bi >> 10, i = bi & 1023;
    const int tid = threadIdx.x;
    const int lane = tid & 31, warp = tid >> 5;

    float sacc[4] = {0.f, 0.f, 0.f, 0.f};

    for (int h = 0; h < NH; h++) {
        const int bh = b * NH + h;
        const float* srow = gS + ((size_t)bh * SEQ + i) * SEQ;
        const float* vwp  = gVW + (size_t)bh * SEQ;

        float e[4];
        float m = -1e30f;
#pragma unroll
        for (int l = 0; l < 4; l++) {
            e[l] = srow[tid + l * 256];
            m = fmaxf(m, e[l]);
        }
        m = warpMax(m);
        if (lane == 0) redm[warp] = m;
        __syncthreads();
        float gm = redm[0];
#pragma unroll
        for (int w = 1; w < 8; w++) gm = fmaxf(gm, redm[w]);

        float psum = 0.f;
#pragma unroll
        for (int l = 0; l < 4; l++) {
            e[l] = __expf(e[l] - gm);
            psum += e[l];
        }
        psum = warpSum(psum);
        if (lane == 0) reds[warp] = psum;
        __syncthreads();
        float gsum = reds[0];
#pragma unroll
        for (int w = 1; w < 8; w++) gsum += reds[w];
        float inv = 1.0f / gsum;

#pragma unroll
        for (int l = 0; l < 4; l++)
            sacc[l] += e[l] * inv * vwp[tid + l * 256];
        __syncthreads();
    }

    float o0 = 0.f, o1 = 0.f, o2 = 0.f;
    const float* dp = dirs + ((size_t)(b * SEQ + i)) * SEQ * 3;
#pragma unroll
    for (int l = 0; l < 4; l++) {
        int j = tid + l * 256;
        float s = sacc[l];
        o0 = fmaf(s, dp[j * 3 + 0], o0);
        o1 = fmaf(s, dp[j * 3 + 1], o1);
        o2 = fmaf(s, dp[j * 3 + 2], o2);
    }
    o0 = warpSum(o0); o1 = warpSum(o1); o2 = warpSum(o2);
    if (lane == 0) { redo[0][warp] = o0; redo[1][warp] = o1; redo[2][warp] = o2; }
    __syncthreads();
    if (tid < 3) {
        float r = 0.f;
#pragma unroll
        for (int w = 0; w < 8; w++) r += redo[tid][w];
        out[(size_t)bi * 3 + tid] = r + bf[0];
    }
}

// ============================================================
extern "C" void kernel_launch(void* const* d_in, const int* in_sizes, int n_in,
                              void* d_out, int out_size)
{
    const float* emb   = (const float*)d_in[0];  // (4,1024,512)
    const float* dirs  = (const float*)d_in[1];  // (4,1024,1024,3)
    const float* dmask = (const float*)d_in[2];  // (32,1024,1024)
    const float* Wp    = (const float*)d_in[3];  // (512,1536)
    const float* bp    = (const float*)d_in[4];  // (1536,)
    const float* wf    = (const float*)d_in[5];  // (512,)
    const float* bf    = (const float*)d_in[6];  // (1,)
    float* out = (float*)d_out;                  // (4,1024,3)

    qkv_mma<<<dim3(12, 32), 256>>>(emb, Wp, bp);
    vw_kernel<<<BATCH * NH * SEQ / 8, 256>>>(wf);
    scores_mma<<<dim3(8, 8, BATCH * NH), 256>>>(dmask);
    out_kernel<<<BATCH * SEQ, 256>>>(dirs, bf, out);
}

// round 5
// speedup vs baseline: 1.4400x; 1.1047x over previous
#include <cuda_runtime.h>
#include <cuda_bf16.h>
#include <stdint.h>
#include <math.h>

#define NH     8
#define BATCH  4
#define SEQ    1024
#define DMODEL 512
#define DH     64
#define SCALEQ 0.04419417382415922f  // 1/sqrt(512)

// ---- scratch (device globals; no allocation allowed) ----
__device__ float gQ[BATCH * NH * SEQ * DH];          // pre-scaled by 1/sqrt(d)
__device__ float gK[BATCH * NH * SEQ * DH];
__device__ float gV[BATCH * NH * SEQ * DH];
__device__ float gVW[BATCH * NH * SEQ];

// ============================================================
// bf16 helpers
// ============================================================
__device__ __forceinline__ void split_bf16(float x, __nv_bfloat16& h, __nv_bfloat16& l) {
    h = __float2bfloat16(x);
    l = __float2bfloat16(x - __bfloat162float(h));
}
__device__ __forceinline__ uint32_t pack2(__nv_bfloat16 a, __nv_bfloat16 b) {
    __nv_bfloat162 t; t.x = a; t.y = b;
    return *(uint32_t*)&t;
}

__device__ __forceinline__ void mma_bf16(float c[4], uint32_t a0, uint32_t a1,
                                         uint32_t a2, uint32_t a3,
                                         uint32_t b0, uint32_t b1) {
    asm volatile(
        "mma.sync.aligned.m16n8k16.row.col.f32.bf16.bf16.f32 "
        "{%0,%1,%2,%3}, {%4,%5,%6,%7}, {%8,%9}, {%0,%1,%2,%3};"
        : "+f"(c[0]), "+f"(c[1]), "+f"(c[2]), "+f"(c[3])
        : "r"(a0), "r"(a1), "r"(a2), "r"(a3), "r"(b0), "r"(b1));
}

// SMEM tile stride for GEMM staging (32-k chunks): 40 bf16 elements
#define TS 40

// ============================================================
// K1: qkv = emb(4096x512) @ W(512x1536) + bias, scatter to Q/K/V.
// ============================================================
__device__ __forceinline__ void mma_pass(
    const __nv_bfloat16* __restrict__ A, const __nv_bfloat16* __restrict__ B,
    float c[2][8][4], int wM, int wN, int lane)
{
    const int r  = lane >> 2;
    const int cq = (lane & 3) * 2;
#pragma unroll
    for (int ks = 0; ks < 2; ks++) {
        const int k0 = ks * 16;
        uint32_t a[2][4];
#pragma unroll
        for (int mt = 0; mt < 2; mt++) {
            const int rb = wM * 32 + mt * 16 + r;
            a[mt][0] = *(const uint32_t*)(A + rb * TS + k0 + cq);
            a[mt][1] = *(const uint32_t*)(A + (rb + 8) * TS + k0 + cq);
            a[mt][2] = *(const uint32_t*)(A + rb * TS + k0 + cq + 8);
            a[mt][3] = *(const uint32_t*)(A + (rb + 8) * TS + k0 + cq + 8);
        }
#pragma unroll
        for (int nt = 0; nt < 8; nt++) {
            const int nb = wN * 64 + nt * 8 + r;
            uint32_t b0 = *(const uint32_t*)(B + nb * TS + k0 + cq);
            uint32_t b1 = *(const uint32_t*)(B + nb * TS + k0 + cq + 8);
#pragma unroll
            for (int mt = 0; mt < 2; mt++)
                mma_bf16(c[mt][nt], a[mt][0], a[mt][1], a[mt][2], a[mt][3], b0, b1);
        }
    }
}

__device__ __forceinline__ void load_rows_g(const float* __restrict__ src, int rs,
                                            int tid, float4 rg[4])
{
#pragma unroll
    for (int l = 0; l < 4; l++) {
        int idx = tid + l * 256;
        int row = idx >> 3, c4 = idx & 7;
        rg[l] = *(const float4*)(src + (size_t)row * rs + (c4 << 2));
    }
}
__device__ __forceinline__ void store_rows_s(__nv_bfloat16* hi, __nv_bfloat16* lo,
                                             int tid, const float4 rg[4])
{
#pragma unroll
    for (int l = 0; l < 4; l++) {
        int idx = tid + l * 256;
        int row = idx >> 3, c4 = idx & 7;
        int base = row * TS + (c4 << 2);
        float v[4] = {rg[l].x, rg[l].y, rg[l].z, rg[l].w};
        __nv_bfloat16 h[4], e[4];
#pragma unroll
        for (int j = 0; j < 4; j++) split_bf16(v[j], h[j], e[j]);
        *(uint32_t*)(hi + base)     = pack2(h[0], h[1]);
        *(uint32_t*)(hi + base + 2) = pack2(h[2], h[3]);
        *(uint32_t*)(lo + base)     = pack2(e[0], e[1]);
        *(uint32_t*)(lo + base + 2) = pack2(e[2], e[3]);
    }
}

__global__ __launch_bounds__(256) void qkv_mma(
    const float* __restrict__ A, const float* __restrict__ W,
    const float* __restrict__ bias)
{
    __shared__ __nv_bfloat16 Ah[128 * TS], Al[128 * TS];
    __shared__ __nv_bfloat16 Bh[128 * TS], Bl[128 * TS];
    __shared__ float bias_sm[128];

    const int tid = threadIdx.x;
    const int wid = tid >> 5, lane = tid & 31;
    const int wM = wid & 3, wN = wid >> 2;
    const int bx = blockIdx.x, by = blockIdx.y;

    if (tid < 128) bias_sm[tid] = bias[bx * 128 + tid];

    float c[2][8][4];
#pragma unroll
    for (int mt = 0; mt < 2; mt++)
#pragma unroll
        for (int nt = 0; nt < 8; nt++)
#pragma unroll
            for (int j = 0; j < 4; j++) c[mt][nt][j] = 0.f;

    const float* Abase = A + (size_t)(by * 128) * 512;
    float4 ra[4], rb[4];
    load_rows_g(Abase, 512, tid, ra);
#pragma unroll
    for (int l = 0; l < 4; l++) {
        int idx = tid + l * 256;
        int kr = idx >> 5, c4 = idx & 31;
        rb[l] = *(const float4*)(W + (size_t)kr * 1536 + bx * 128 + (c4 << 2));
    }

    for (int ch = 0; ch < 16; ch++) {
        store_rows_s(Ah, Al, tid, ra);
#pragma unroll
        for (int l = 0; l < 4; l++) {
            int idx = tid + l * 256;
            int kr = idx >> 5, c4 = idx & 31;
            float v[4] = {rb[l].x, rb[l].y, rb[l].z, rb[l].w};
#pragma unroll
            for (int j = 0; j < 4; j++) {
                int n = (c4 << 2) + j;
                __nv_bfloat16 h, e;
                split_bf16(v[j], h, e);
                Bh[n * TS + kr] = h;
                Bl[n * TS + kr] = e;
            }
        }
        __syncthreads();

        if (ch < 15) {
            load_rows_g(Abase + (ch + 1) * 32, 512, tid, ra);
#pragma unroll
            for (int l = 0; l < 4; l++) {
                int idx = tid + l * 256;
                int kr = idx >> 5, c4 = idx & 31;
                rb[l] = *(const float4*)(W + (size_t)((ch + 1) * 32 + kr) * 1536
                                           + bx * 128 + (c4 << 2));
            }
        }

        mma_pass(Ah, Bh, c, wM, wN, lane);
        mma_pass(Ah, Bl, c, wM, wN, lane);
        mma_pass(Al, Bh, c, wM, wN, lane);
        __syncthreads();
    }

    const int r  = lane >> 2;
    const int cq = (lane & 3) * 2;
#pragma unroll
    for (int nt = 0; nt < 8; nt++) {
        const int lcol = wN * 64 + nt * 8 + cq;
        const int gcol = bx * 128 + lcol;
        const int which = gcol >> 9;
        const int idx = gcol & 511;
        const int h = idx >> 6, w = idx & 63;
        const float sc = (which == 0) ? SCALEQ : 1.0f;
        const float b0 = bias_sm[lcol], b1 = bias_sm[lcol + 1];
        float* p = (which == 0) ? gQ : (which == 1) ? gK : gV;
#pragma unroll
        for (int mt = 0; mt < 2; mt++) {
            const int grow = by * 128 + wM * 32 + mt * 16 + r;
            const int bb = grow >> 10, ii = grow & 1023;
            size_t dst = (((size_t)(bb * NH + h) * SEQ) + ii) * DH + w;
            float2 v0 = make_float2((c[mt][nt][0] + b0) * sc, (c[mt][nt][1] + b1) * sc);
            float2 v1 = make_float2((c[mt][nt][2] + b0) * sc, (c[mt][nt][3] + b1) * sc);
            *(float2*)(p + dst) = v0;
            *(float2*)(p + dst + (size_t)8 * DH) = v1;
        }
    }
}

// ============================================================
// K2: vw[b,h,j] = sum_w V[b,h,j,w] * w_force[h*64+w]
// ============================================================
__global__ __launch_bounds__(256) void vw_kernel(const float* __restrict__ wf)
{
    int warp = threadIdx.x >> 5;
    int lane = threadIdx.x & 31;
    int row = blockIdx.x * 8 + warp;
    int h = (row >> 10) & 7;
    const float* vrow = gV + (size_t)row * DH;
    float s = vrow[lane] * wf[h * 64 + lane] + vrow[lane + 32] * wf[h * 64 + lane + 32];
#pragma unroll
    for (int o = 16; o; o >>= 1) s += __shfl_xor_sync(0xffffffffu, s, o);
    if (lane == 0) gVW[row] = s;
}

// ============================================================
// K3 (fused): per (b, i-tile of 32):
//   for each h: S(32x1024) = Q @ K^T + mask (registers, 8 warps x 128 j),
//   block softmax, wsum[i][j] += attn * vw_h[j]; then out = wsum contracted
//   with dirs + b_force. Deletes the 128MB gS round-trip.
// Q tile stride QS = 72 bf16 (64 cols + 8 pad) -- conflict-free fragments.
// SMEM layout (bytes):
//   wsum   [32][1028] f32 : 0      .. 131584
//   Qhi    [32][72] bf16  : 131584 .. 136192
//   Qlo    [32][72] bf16  : 136192 .. 140800
//   vwsm   [1024] f32     : 140800 .. 144896
//   redm   [32][8] f32    : 144896 .. 145920
//   redl   [32][8] f32    : 145920 .. 146944
// ============================================================
#define QS 72
#define WSTRIDE 1028
#define FUSED_SMEM 146944

__global__ __launch_bounds__(256, 1) void fused_attn(
    const float* __restrict__ dmask, const float* __restrict__ dirs,
    const float* __restrict__ bf, float* __restrict__ out)
{
    extern __shared__ char sm[];
    float* wsum = (float*)sm;
    __nv_bfloat16* Qhi = (__nv_bfloat16*)(sm + 131584);
    __nv_bfloat16* Qlo = (__nv_bfloat16*)(sm + 136192);
    float* vwsm = (float*)(sm + 140800);
    float* redm = (float*)(sm + 144896);
    float* redl = (float*)(sm + 145920);

    const int tid = threadIdx.x, wid = tid >> 5, lane = tid & 31;
    const int r = lane >> 2, cq = (lane & 3) * 2;
    const int b = blockIdx.x >> 5;
    const int i0 = (blockIdx.x & 31) * 32;
    const int jbase = wid * 128;

    // zero wsum
    for (int idx = tid; idx < 32 * WSTRIDE; idx += 256) wsum[idx] = 0.f;

    for (int h = 0; h < NH; h++) {
        const int bh = b * NH + h;
        __syncthreads();   // wsum init / prev-h SMEM reuse

        // stage Q tile hi/lo + vw
        {
            const float* Qb = gQ + ((size_t)bh * SEQ + i0) * DH;
#pragma unroll
            for (int l = 0; l < 2; l++) {
                int idx = tid + l * 256;            // 512 float4 groups
                int row = idx >> 4, c4 = idx & 15;  // row 0..31, c4 0..15
                float4 v = *(const float4*)(Qb + (size_t)row * DH + (c4 << 2));
                int base = row * QS + (c4 << 2);
                float vv[4] = {v.x, v.y, v.z, v.w};
                __nv_bfloat16 hh[4], ee[4];
#pragma unroll
                for (int j = 0; j < 4; j++) split_bf16(vv[j], hh[j], ee[j]);
                *(uint32_t*)(Qhi + base)     = pack2(hh[0], hh[1]);
                *(uint32_t*)(Qhi + base + 2) = pack2(hh[2], hh[3]);
                *(uint32_t*)(Qlo + base)     = pack2(ee[0], ee[1]);
                *(uint32_t*)(Qlo + base + 2) = pack2(ee[2], ee[3]);
            }
            float4 vv = *(const float4*)(gVW + (size_t)bh * SEQ + tid * 4);
            *(float4*)(vwsm + tid * 4) = vv;
        }
        __syncthreads();

        // S = Q @ K^T  (K fragments straight from global, inline hi/lo split)
        float c[2][16][4];
#pragma unroll
        for (int mt = 0; mt < 2; mt++)
#pragma unroll
            for (int nt = 0; nt < 16; nt++)
#pragma unroll
                for (int e = 0; e < 4; e++) c[mt][nt][e] = 0.f;

        const float* Kb = gK + (size_t)bh * SEQ * DH;
#pragma unroll
        for (int ks = 0; ks < 4; ks++) {
            const int k0 = ks * 16;
            uint32_t ah[2][4], al[2][4];
#pragma unroll
            for (int mt = 0; mt < 2; mt++) {
                const int rb = mt * 16 + r;
                ah[mt][0] = *(const uint32_t*)(Qhi + rb * QS + k0 + cq);
                ah[mt][1] = *(const uint32_t*)(Qhi + (rb + 8) * QS + k0 + cq);
                ah[mt][2] = *(const uint32_t*)(Qhi + rb * QS + k0 + cq + 8);
                ah[mt][3] = *(const uint32_t*)(Qhi + (rb + 8) * QS + k0 + cq + 8);
                al[mt][0] = *(const uint32_t*)(Qlo + rb * QS + k0 + cq);
                al[mt][1] = *(const uint32_t*)(Qlo + (rb + 8) * QS + k0 + cq);
                al[mt][2] = *(const uint32_t*)(Qlo + rb * QS + k0 + cq + 8);
                al[mt][3] = *(const uint32_t*)(Qlo + (rb + 8) * QS + k0 + cq + 8);
            }
#pragma unroll
            for (int nt = 0; nt < 16; nt++) {
                const int j = jbase + nt * 8 + r;
                const float* kp = Kb + (size_t)j * DH + k0 + cq;
                float2 v0 = *(const float2*)(kp);
                float2 v1 = *(const float2*)(kp + 8);
                __nv_bfloat16 h0, e0, h1, e1, h2, e2, h3, e3;
                split_bf16(v0.x, h0, e0); split_bf16(v0.y, h1, e1);
                split_bf16(v1.x, h2, e2); split_bf16(v1.y, h3, e3);
                uint32_t bh0 = pack2(h0, h1), bh1 = pack2(h2, h3);
                uint32_t bl0 = pack2(e0, e1), bl1 = pack2(e2, e3);
#pragma unroll
                for (int mt = 0; mt < 2; mt++) {
                    mma_bf16(c[mt][nt], ah[mt][0], ah[mt][1], ah[mt][2], ah[mt][3], bh0, bh1);
                    mma_bf16(c[mt][nt], ah[mt][0], ah[mt][1], ah[mt][2], ah[mt][3], bl0, bl1);
                    mma_bf16(c[mt][nt], al[mt][0], al[mt][1], al[mt][2], al[mt][3], bh0, bh1);
                }
            }
        }

        // add mask + row max
        float tmax[4] = {-1e30f, -1e30f, -1e30f, -1e30f};
#pragma unroll
        for (int mt = 0; mt < 2; mt++) {
#pragma unroll
            for (int half = 0; half < 2; half++) {
                const int lrow = mt * 16 + half * 8 + r;
                const size_t rowaddr = ((size_t)bh * SEQ + (i0 + lrow)) * SEQ + jbase + cq;
                float tm = -1e30f;
#pragma unroll
                for (int nt = 0; nt < 16; nt++) {
                    float2 m = *(const float2*)(dmask + rowaddr + nt * 8);
                    float x0 = c[mt][nt][half * 2]     + m.x;
                    float x1 = c[mt][nt][half * 2 + 1] + m.y;
                    c[mt][nt][half * 2]     = x0;
                    c[mt][nt][half * 2 + 1] = x1;
                    tm = fmaxf(tm, fmaxf(x0, x1));
                }
                tmax[mt * 2 + half] = tm;
            }
        }
#pragma unroll
        for (int e = 0; e < 4; e++) {
            tmax[e] = fmaxf(tmax[e], __shfl_xor_sync(0xffffffffu, tmax[e], 1));
            tmax[e] = fmaxf(tmax[e], __shfl_xor_sync(0xffffffffu, tmax[e], 2));
        }
        if ((lane & 3) == 0) {
#pragma unroll
            for (int mt = 0; mt < 2; mt++)
#pragma unroll
                for (int half = 0; half < 2; half++)
                    redm[(mt * 16 + half * 8 + r) * 8 + wid] = tmax[mt * 2 + half];
        }
        __syncthreads();

        float mf[4];
#pragma unroll
        for (int mt = 0; mt < 2; mt++)
#pragma unroll
            for (int half = 0; half < 2; half++) {
                const float* rp = redm + (mt * 16 + half * 8 + r) * 8;
                float mm = rp[0];
#pragma unroll
                for (int w = 1; w < 8; w++) mm = fmaxf(mm, rp[w]);
                mf[mt * 2 + half] = mm;
            }

        // exp + row sum
        float tsum[4] = {0.f, 0.f, 0.f, 0.f};
#pragma unroll
        for (int mt = 0; mt < 2; mt++)
#pragma unroll
            for (int nt = 0; nt < 16; nt++) {
#pragma unroll
                for (int half = 0; half < 2; half++) {
                    float p0 = __expf(c[mt][nt][half * 2]     - mf[mt * 2 + half]);
                    float p1 = __expf(c[mt][nt][half * 2 + 1] - mf[mt * 2 + half]);
                    c[mt][nt][half * 2]     = p0;
                    c[mt][nt][half * 2 + 1] = p1;
                    tsum[mt * 2 + half] += p0 + p1;
                }
            }
#pragma unroll
        for (int e = 0; e < 4; e++) {
            tsum[e] += __shfl_xor_sync(0xffffffffu, tsum[e], 1);
            tsum[e] += __shfl_xor_sync(0xffffffffu, tsum[e], 2);
        }
        if ((lane & 3) == 0) {
#pragma unroll
            for (int mt = 0; mt < 2; mt++)
#pragma unroll
                for (int half = 0; half < 2; half++)
                    redl[(mt * 16 + half * 8 + r) * 8 + wid] = tsum[mt * 2 + half];
        }
        __syncthreads();

        float inv[4];
#pragma unroll
        for (int mt = 0; mt < 2; mt++)
#pragma unroll
            for (int half = 0; half < 2; half++) {
                const float* rp = redl + (mt * 16 + half * 8 + r) * 8;
                float ss = rp[0];
#pragma unroll
                for (int w = 1; w < 8; w++) ss += rp[w];
                inv[mt * 2 + half] = 1.0f / ss;
            }

        // wsum += attn * vw
#pragma unroll
        for (int nt = 0; nt < 16; nt++) {
            const int jl = jbase + nt * 8 + cq;
            float2 vw2 = *(const float2*)(vwsm + jl);
#pragma unroll
            for (int mt = 0; mt < 2; mt++)
#pragma unroll
                for (int half = 0; half < 2; half++) {
                    const int lrow = mt * 16 + half * 8 + r;
                    float* wp = wsum + lrow * WSTRIDE + jl;
                    float2 w = *(float2*)wp;
                    float iv = inv[mt * 2 + half];
                    w.x += c[mt][nt][half * 2]     * iv * vw2.x;
                    w.y += c[mt][nt][half * 2 + 1] * iv * vw2.y;
                    *(float2*)wp = w;
                }
        }
    }
    __syncthreads();

    // dirs contraction: warp wid owns rows 4*wid .. 4*wid+3
    const float bias = bf[0];
#pragma unroll
    for (int rr = 0; rr < 4; rr++) {
        const int ii = wid * 4 + rr;
        const float* dp = dirs + ((size_t)(b * SEQ + i0 + ii)) * SEQ * 3;
        const float* wrow = wsum + ii * WSTRIDE;
        float a0 = 0.f, a1 = 0.f, a2 = 0.f;
#pragma unroll
        for (int t = 0; t < 8; t++) {
            const int jb = (lane + t * 32) * 4;           // 4 js per lane
            const float* dpe = dp + (size_t)jb * 3;
            float4 f0 = *(const float4*)(dpe);
            float4 f1 = *(const float4*)(dpe + 4);
            float4 f2 = *(const float4*)(dpe + 8);
            float4 w4 = *(const float4*)(wrow + jb);
            a0 = fmaf(f0.x, w4.x, a0); a1 = fmaf(f0.y, w4.x, a1); a2 = fmaf(f0.z, w4.x, a2);
            a0 = fmaf(f0.w, w4.y, a0); a1 = fmaf(f1.x, w4.y, a1); a2 = fmaf(f1.y, w4.y, a2);
            a0 = fmaf(f1.z, w4.z, a0); a1 = fmaf(f1.w, w4.z, a1); a2 = fmaf(f2.x, w4.z, a2);
            a0 = fmaf(f2.y, w4.w, a0); a1 = fmaf(f2.z, w4.w, a1); a2 = fmaf(f2.w, w4.w, a2);
        }
#pragma unroll
        for (int o = 16; o; o >>= 1) {
            a0 += __shfl_xor_sync(0xffffffffu, a0, o);
            a1 += __shfl_xor_sync(0xffffffffu, a1, o);
            a2 += __shfl_xor_sync(0xffffffffu, a2, o);
        }
        if (lane == 0) {
            float* op = out + ((size_t)(b * SEQ + i0 + ii)) * 3;
            op[0] = a0 + bias;
            op[1] = a1 + bias;
            op[2] = a2 + bias;
        }
    }
}

// ============================================================
extern "C" void kernel_launch(void* const* d_in, const int* in_sizes, int n_in,
                              void* d_out, int out_size)
{
    const float* emb   = (const float*)d_in[0];  // (4,1024,512)
    const float* dirs  = (const float*)d_in[1];  // (4,1024,1024,3)
    const float* dmask = (const float*)d_in[2];  // (32,1024,1024)
    const float* Wp    = (const float*)d_in[3];  // (512,1536)
    const float* bp    = (const float*)d_in[4];  // (1536,)
    const float* wf    = (const float*)d_in[5];  // (512,)
    const float* bf    = (const float*)d_in[6];  // (1,)
    float* out = (float*)d_out;                  // (4,1024,3)

    cudaFuncSetAttribute(fused_attn, cudaFuncAttributeMaxDynamicSharedMemorySize,
                         FUSED_SMEM);

    qkv_mma<<<dim3(12, 32), 256>>>(emb, Wp, bp);
    vw_kernel<<<BATCH * NH * SEQ / 8, 256>>>(wf);
    fused_attn<<<BATCH * 32, 256, FUSED_SMEM>>>(dmask, dirs, bf, out);
}

// round 6
// speedup vs baseline: 1.8542x; 1.2876x over previous
#include <cuda_runtime.h>
#include <cuda_bf16.h>
#include <stdint.h>
#include <math.h>

#define NH     8
#define BATCH  4
#define SEQ    1024
#define DMODEL 512
#define DH     64
#define SCALEQ 0.04419417382415922f  // 1/sqrt(512)

// ---- scratch (device globals; no allocation allowed) ----
__device__ __nv_bfloat16 gAhi[4096 * 512];   // emb hi
__device__ __nv_bfloat16 gAlo[4096 * 512];   // emb lo
__device__ __nv_bfloat16 gWhi[1536 * 512];   // W^T hi  [n][k]
__device__ __nv_bfloat16 gWlo[1536 * 512];   // W^T lo
__device__ __nv_bfloat16 gQhi[BATCH * NH * SEQ * DH];
__device__ __nv_bfloat16 gQlo[BATCH * NH * SEQ * DH];
__device__ __nv_bfloat16 gKhi[BATCH * NH * SEQ * DH];
__device__ __nv_bfloat16 gKlo[BATCH * NH * SEQ * DH];
__device__ float gV[BATCH * NH * SEQ * DH];
__device__ float gVW[BATCH * NH * SEQ];

// ============================================================
// helpers
// ============================================================
__device__ __forceinline__ uint32_t smem_u32(const void* p) {
    uint32_t a;
    asm("{ .reg .u64 t; cvta.to.shared.u64 t, %1; cvt.u32.u64 %0, t; }"
        : "=r"(a) : "l"(p));
    return a;
}
__device__ __forceinline__ void split_bf16(float x, __nv_bfloat16& h, __nv_bfloat16& l) {
    h = __float2bfloat16(x);
    l = __float2bfloat16(x - __bfloat162float(h));
}
__device__ __forceinline__ uint32_t pack2(__nv_bfloat16 a, __nv_bfloat16 b) {
    __nv_bfloat162 t; t.x = a; t.y = b;
    return *(uint32_t*)&t;
}
__device__ __forceinline__ void mma_bf16(float c[4], uint32_t a0, uint32_t a1,
                                         uint32_t a2, uint32_t a3,
                                         uint32_t b0, uint32_t b1) {
    asm volatile(
        "mma.sync.aligned.m16n8k16.row.col.f32.bf16.bf16.f32 "
        "{%0,%1,%2,%3}, {%4,%5,%6,%7}, {%8,%9}, {%0,%1,%2,%3};"
        : "+f"(c[0]), "+f"(c[1]), "+f"(c[2]), "+f"(c[3])
        : "r"(a0), "r"(a1), "r"(a2), "r"(a3), "r"(b0), "r"(b1));
}
__device__ __forceinline__ void cp_async16(uint32_t dst, const void* src) {
    asm volatile("cp.async.cg.shared.global [%0], [%1], 16;" :: "r"(dst), "l"(src));
}
__device__ __forceinline__ void cp_commit() {
    asm volatile("cp.async.commit_group;");
}

// ============================================================
// P1: split emb -> gAhi/gAlo
// ============================================================
__global__ __launch_bounds__(256) void prep_emb(const float* __restrict__ emb)
{
    size_t i = ((size_t)blockIdx.x * 256 + threadIdx.x) * 4;
    float4 v = *(const float4*)(emb + i);
    __nv_bfloat16 h[4], l[4];
    split_bf16(v.x, h[0], l[0]); split_bf16(v.y, h[1], l[1]);
    split_bf16(v.z, h[2], l[2]); split_bf16(v.w, h[3], l[3]);
    uint2 uh = make_uint2(pack2(h[0], h[1]), pack2(h[2], h[3]));
    uint2 ul = make_uint2(pack2(l[0], l[1]), pack2(l[2], l[3]));
    *(uint2*)(gAhi + i) = uh;
    *(uint2*)(gAlo + i) = ul;
}

// ============================================================
// P2: transpose+split W (512x1536) -> gWhi/gWlo [1536][512]
// ============================================================
__global__ __launch_bounds__(256) void prep_W(const float* __restrict__ W)
{
    __shared__ float t[32][33];
    const int n0 = blockIdx.x * 32, k0 = blockIdx.y * 32;
    const int tx = threadIdx.x & 31, ty = threadIdx.x >> 5;
#pragma unroll
    for (int it = 0; it < 4; it++)
        t[ty + it * 8][tx] = W[(size_t)(k0 + ty + it * 8) * 1536 + n0 + tx];
    __syncthreads();
#pragma unroll
    for (int it = 0; it < 4; it++) {
        int n = ty + it * 8;
        float v = t[tx][n];
        __nv_bfloat16 h, l;
        split_bf16(v, h, l);
        gWhi[(size_t)(n0 + n) * 512 + k0 + tx] = h;
        gWlo[(size_t)(n0 + n) * 512 + k0 + tx] = l;
    }
}

// ============================================================
// K1: qkv GEMM via cp.async double-buffered bf16 tiles.
// 128x128 tile, BK=32, stages of {Ah,Al,Bh,Bl} 10240B each.
// ============================================================
#define TS 40
#define TILE_B  (128 * TS * 2)          // 10240
#define STAGE_B (4 * TILE_B)            // 40960
#define QKV_SMEM (2 * STAGE_B + 512)    // + bias

__device__ __forceinline__ void mma_pass(
    const __nv_bfloat16* __restrict__ A, const __nv_bfloat16* __restrict__ B,
    float c[2][8][4], int wM, int wN, int lane)
{
    const int r  = lane >> 2;
    const int cq = (lane & 3) * 2;
#pragma unroll
    for (int ks = 0; ks < 2; ks++) {
        const int k0 = ks * 16;
        uint32_t a[2][4];
#pragma unroll
        for (int mt = 0; mt < 2; mt++) {
            const int rb = wM * 32 + mt * 16 + r;
            a[mt][0] = *(const uint32_t*)(A + rb * TS + k0 + cq);
            a[mt][1] = *(const uint32_t*)(A + (rb + 8) * TS + k0 + cq);
            a[mt][2] = *(const uint32_t*)(A + rb * TS + k0 + cq + 8);
            a[mt][3] = *(const uint32_t*)(A + (rb + 8) * TS + k0 + cq + 8);
        }
#pragma unroll
        for (int nt = 0; nt < 8; nt++) {
            const int nb = wN * 64 + nt * 8 + r;
            uint32_t b0 = *(const uint32_t*)(B + nb * TS + k0 + cq);
            uint32_t b1 = *(const uint32_t*)(B + nb * TS + k0 + cq + 8);
#pragma unroll
            for (int mt = 0; mt < 2; mt++)
                mma_bf16(c[mt][nt], a[mt][0], a[mt][1], a[mt][2], a[mt][3], b0, b1);
        }
    }
}

__global__ __launch_bounds__(256, 2) void qkv_cp(const float* __restrict__ bias)
{
    extern __shared__ char sm[];
    float* bias_sm = (float*)(sm + 2 * STAGE_B);
    const uint32_t base = smem_u32(sm);

    const int tid = threadIdx.x;
    const int wid = tid >> 5, lane = tid & 31;
    const int wM = wid & 3, wN = wid >> 2;
    const int bx = blockIdx.x, by = blockIdx.y;

    if (tid < 128) bias_sm[tid] = bias[bx * 128 + tid];

    const __nv_bfloat16* srcs[4] = {
        gAhi + (size_t)(by * 128) * 512,
        gAlo + (size_t)(by * 128) * 512,
        gWhi + (size_t)(bx * 128) * 512,
        gWlo + (size_t)(bx * 128) * 512
    };

    float c[2][8][4];
#pragma unroll
    for (int mt = 0; mt < 2; mt++)
#pragma unroll
        for (int nt = 0; nt < 8; nt++)
#pragma unroll
            for (int j = 0; j < 4; j++) c[mt][nt][j] = 0.f;

    // issue one stage: 2048 cp.async of 16B (8/thread)
    auto issue = [&](int ch, int s) {
        const uint32_t sb = base + s * STAGE_B;
#pragma unroll
        for (int l = 0; l < 8; l++) {
            int idx = tid + l * 256;
            int tile = idx >> 9;
            int rem = idx & 511;
            int row = rem >> 2, chunk = rem & 3;
            uint32_t dst = sb + tile * TILE_B + row * (TS * 2) + chunk * 16;
            const __nv_bfloat16* src = srcs[tile] + (size_t)row * 512 + ch * 32 + chunk * 8;
            cp_async16(dst, src);
        }
        cp_commit();
    };

    issue(0, 0);
    for (int ch = 0; ch < 16; ch++) {
        const int s = ch & 1;
        if (ch < 15) {
            issue(ch + 1, s ^ 1);
            asm volatile("cp.async.wait_group 1;");
        } else {
            asm volatile("cp.async.wait_group 0;");
        }
        __syncthreads();

        const __nv_bfloat16* Ah = (const __nv_bfloat16*)(sm + s * STAGE_B);
        const __nv_bfloat16* Al = Ah + 128 * TS;
        const __nv_bfloat16* Bh = Al + 128 * TS;
        const __nv_bfloat16* Bl = Bh + 128 * TS;
        mma_pass(Ah, Bh, c, wM, wN, lane);
        mma_pass(Ah, Bl, c, wM, wN, lane);
        mma_pass(Al, Bh, c, wM, wN, lane);
        __syncthreads();
    }

    // Epilogue: bias (+Q scale); Q/K stored split bf16, V fp32.
    const int r  = lane >> 2;
    const int cq = (lane & 3) * 2;
#pragma unroll
    for (int nt = 0; nt < 8; nt++) {
        const int lcol = wN * 64 + nt * 8 + cq;
        const int gcol = bx * 128 + lcol;
        const int which = gcol >> 9;
        const int idx = gcol & 511;
        const int h = idx >> 6, w = idx & 63;
        const float sc = (which == 0) ? SCALEQ : 1.0f;
        const float b0 = bias_sm[lcol], b1 = bias_sm[lcol + 1];
#pragma unroll
        for (int mt = 0; mt < 2; mt++) {
            const int grow = by * 128 + wM * 32 + mt * 16 + r;
            const int bb = grow >> 10, ii = grow & 1023;
            size_t dst = (((size_t)(bb * NH + h) * SEQ) + ii) * DH + w;
            float x0 = (c[mt][nt][0] + b0) * sc;
            float x1 = (c[mt][nt][1] + b1) * sc;
            float x2 = (c[mt][nt][2] + b0) * sc;
            float x3 = (c[mt][nt][3] + b1) * sc;
            if (which == 2) {
                *(float2*)(gV + dst) = make_float2(x0, x1);
                *(float2*)(gV + dst + (size_t)8 * DH) = make_float2(x2, x3);
            } else {
                __nv_bfloat16 h0, l0, h1, l1, h2, l2, h3, l3;
                split_bf16(x0, h0, l0); split_bf16(x1, h1, l1);
                split_bf16(x2, h2, l2); split_bf16(x3, h3, l3);
                __nv_bfloat16* ph = (which == 0) ? gQhi : gKhi;
                __nv_bfloat16* pl = (which == 0) ? gQlo : gKlo;
                *(uint32_t*)(ph + dst) = pack2(h0, h1);
                *(uint32_t*)(pl + dst) = pack2(l0, l1);
                *(uint32_t*)(ph + dst + (size_t)8 * DH) = pack2(h2, h3);
                *(uint32_t*)(pl + dst + (size_t)8 * DH) = pack2(l2, l3);
            }
        }
    }
}

// ============================================================
// K2: vw[b,h,j] = sum_w V[b,h,j,w] * w_force[h*64+w]
// ============================================================
__global__ __launch_bounds__(256) void vw_kernel(const float* __restrict__ wf)
{
    int warp = threadIdx.x >> 5;
    int lane = threadIdx.x & 31;
    int row = blockIdx.x * 8 + warp;
    int h = (row >> 10) & 7;
    const float* vrow = gV + (size_t)row * DH;
    float s = vrow[lane] * wf[h * 64 + lane] + vrow[lane + 32] * wf[h * 64 + lane + 32];
#pragma unroll
    for (int o = 16; o; o >>= 1) s += __shfl_xor_sync(0xffffffffu, s, o);
    if (lane == 0) gVW[row] = s;
}

// ============================================================
// K3 (fused): per (b, i-tile of 32): scores+softmax+vw+dirs.
// Q/K already bf16-split in global.
// SMEM: wsum[32][1028] f32 : 0..131584
//       Qhi [32][72] bf16  : 131584..136192
//       Qlo [32][72] bf16  : 136192..140800
//       vwsm[1024] f32     : 140800..144896
//       redm[32][8]        : 144896..145920
//       redl[32][8]        : 145920..146944
// ============================================================
#define QS 72
#define WSTRIDE 1028
#define FUSED_SMEM 146944

__global__ __launch_bounds__(256, 1) void fused_attn(
    const float* __restrict__ dmask, const float* __restrict__ dirs,
    const float* __restrict__ bf, float* __restrict__ out)
{
    extern __shared__ char sm[];
    float* wsum = (float*)sm;
    __nv_bfloat16* Qhi = (__nv_bfloat16*)(sm + 131584);
    __nv_bfloat16* Qlo = (__nv_bfloat16*)(sm + 136192);
    float* vwsm = (float*)(sm + 140800);
    float* redm = (float*)(sm + 144896);
    float* redl = (float*)(sm + 145920);

    const int tid = threadIdx.x, wid = tid >> 5, lane = tid & 31;
    const int r = lane >> 2, cq = (lane & 3) * 2;
    const int b = blockIdx.x >> 5;
    const int i0 = (blockIdx.x & 31) * 32;
    const int jbase = wid * 128;

    for (int idx = tid; idx < 32 * WSTRIDE; idx += 256) wsum[idx] = 0.f;

    for (int h = 0; h < NH; h++) {
        const int bh = b * NH + h;
        __syncthreads();

        // stage Q tile (already split) + vw
        {
            const __nv_bfloat16* Qhb = gQhi + ((size_t)bh * SEQ + i0) * DH;
            const __nv_bfloat16* Qlb = gQlo + ((size_t)bh * SEQ + i0) * DH;
            int row = tid >> 3, cc = tid & 7;         // 32 rows x 8 chunks of 8
            *(uint4*)(Qhi + row * QS + cc * 8) = *(const uint4*)(Qhb + row * DH + cc * 8);
            *(uint4*)(Qlo + row * QS + cc * 8) = *(const uint4*)(Qlb + row * DH + cc * 8);
            float4 vv = *(const float4*)(gVW + (size_t)bh * SEQ + tid * 4);
            *(float4*)(vwsm + tid * 4) = vv;
        }
        __syncthreads();

        // S = Q @ K^T  (K bf16 fragments straight from global)
        float c[2][16][4];
#pragma unroll
        for (int mt = 0; mt < 2; mt++)
#pragma unroll
            for (int nt = 0; nt < 16; nt++)
#pragma unroll
                for (int e = 0; e < 4; e++) c[mt][nt][e] = 0.f;

        const __nv_bfloat16* Khb = gKhi + (size_t)bh * SEQ * DH;
        const __nv_bfloat16* Klb = gKlo + (size_t)bh * SEQ * DH;
#pragma unroll
        for (int ks = 0; ks < 4; ks++) {
            const int k0 = ks * 16;
            uint32_t ah[2][4], al[2][4];
#pragma unroll
            for (int mt = 0; mt < 2; mt++) {
                const int rb = mt * 16 + r;
                ah[mt][0] = *(const uint32_t*)(Qhi + rb * QS + k0 + cq);
                ah[mt][1] = *(const uint32_t*)(Qhi + (rb + 8) * QS + k0 + cq);
                ah[mt][2] = *(const uint32_t*)(Qhi + rb * QS + k0 + cq + 8);
                ah[mt][3] = *(const uint32_t*)(Qhi + (rb + 8) * QS + k0 + cq + 8);
                al[mt][0] = *(const uint32_t*)(Qlo + rb * QS + k0 + cq);
                al[mt][1] = *(const uint32_t*)(Qlo + (rb + 8) * QS + k0 + cq);
                al[mt][2] = *(const uint32_t*)(Qlo + rb * QS + k0 + cq + 8);
                al[mt][3] = *(const uint32_t*)(Qlo + (rb + 8) * QS + k0 + cq + 8);
            }
#pragma unroll
            for (int nt = 0; nt < 16; nt++) {
                const int j = jbase + nt * 8 + r;
                const size_t ko = (size_t)j * DH + k0 + cq;
                uint32_t bh0 = *(const uint32_t*)(Khb + ko);
                uint32_t bh1 = *(const uint32_t*)(Khb + ko + 8);
                uint32_t bl0 = *(const uint32_t*)(Klb + ko);
                uint32_t bl1 = *(const uint32_t*)(Klb + ko + 8);
#pragma unroll
                for (int mt = 0; mt < 2; mt++) {
                    mma_bf16(c[mt][nt], ah[mt][0], ah[mt][1], ah[mt][2], ah[mt][3], bh0, bh1);
                    mma_bf16(c[mt][nt], ah[mt][0], ah[mt][1], ah[mt][2], ah[mt][3], bl0, bl1);
                    mma_bf16(c[mt][nt], al[mt][0], al[mt][1], al[mt][2], al[mt][3], bh0, bh1);
                }
            }
        }

        // add mask + row max
        float tmax[4] = {-1e30f, -1e30f, -1e30f, -1e30f};
#pragma unroll
        for (int mt = 0; mt < 2; mt++) {
#pragma unroll
            for (int half = 0; half < 2; half++) {
                const int lrow = mt * 16 + half * 8 + r;
                const size_t rowaddr = ((size_t)bh * SEQ + (i0 + lrow)) * SEQ + jbase + cq;
                float tm = -1e30f;
#pragma unroll
                for (int nt = 0; nt < 16; nt++) {
                    float2 m = *(const float2*)(dmask + rowaddr + nt * 8);
                    float x0 = c[mt][nt][half * 2]     + m.x;
                    float x1 = c[mt][nt][half * 2 + 1] + m.y;
                    c[mt][nt][half * 2]     = x0;
                    c[mt][nt][half * 2 + 1] = x1;
                    tm = fmaxf(tm, fmaxf(x0, x1));
                }
                tmax[mt * 2 + half] = tm;
            }
        }
#pragma unroll
        for (int e = 0; e < 4; e++) {
            tmax[e] = fmaxf(tmax[e], __shfl_xor_sync(0xffffffffu, tmax[e], 1));
            tmax[e] = fmaxf(tmax[e], __shfl_xor_sync(0xffffffffu, tmax[e], 2));
        }
        if ((lane & 3) == 0) {
#pragma unroll
            for (int mt = 0; mt < 2; mt++)
#pragma unroll
                for (int half = 0; half < 2; half++)
                    redm[(mt * 16 + half * 8 + r) * 8 + wid] = tmax[mt * 2 + half];
        }
        __syncthreads();

        float mf[4];
#pragma unroll
        for (int mt = 0; mt < 2; mt++)
#pragma unroll
            for (int half = 0; half < 2; half++) {
                const float* rp = redm + (mt * 16 + half * 8 + r) * 8;
                float mm = rp[0];
#pragma unroll
                for (int w = 1; w < 8; w++) mm = fmaxf(mm, rp[w]);
                mf[mt * 2 + half] = mm;
            }

        // exp + row sum
        float tsum[4] = {0.f, 0.f, 0.f, 0.f};
#pragma unroll
        for (int mt = 0; mt < 2; mt++)
#pragma unroll
            for (int nt = 0; nt < 16; nt++) {
#pragma unroll
                for (int half = 0; half < 2; half++) {
                    float p0 = __expf(c[mt][nt][half * 2]     - mf[mt * 2 + half]);
                    float p1 = __expf(c[mt][nt][half * 2 + 1] - mf[mt * 2 + half]);
                    c[mt][nt][half * 2]     = p0;
                    c[mt][nt][half * 2 + 1] = p1;
                    tsum[mt * 2 + half] += p0 + p1;
                }
            }
#pragma unroll
        for (int e = 0; e < 4; e++) {
            tsum[e] += __shfl_xor_sync(0xffffffffu, tsum[e], 1);
            tsum[e] += __shfl_xor_sync(0xffffffffu, tsum[e], 2);
        }
        if ((lane & 3) == 0) {
#pragma unroll
            for (int mt = 0; mt < 2; mt++)
#pragma unroll
                for (int half = 0; half < 2; half++)
                    redl[(mt * 16 + half * 8 + r) * 8 + wid] = tsum[mt * 2 + half];
        }
        __syncthreads();

        float inv[4];
#pragma unroll
        for (int mt = 0; mt < 2; mt++)
#pragma unroll
            for (int half = 0; half < 2; half++) {
                const float* rp = redl + (mt * 16 + half * 8 + r) * 8;
                float ss = rp[0];
#pragma unroll
                for (int w = 1; w < 8; w++) ss += rp[w];
                inv[mt * 2 + half] = 1.0f / ss;
            }

        // wsum += attn * vw
#pragma unroll
        for (int nt = 0; nt < 16; nt++) {
            const int jl = jbase + nt * 8 + cq;
            float2 vw2 = *(const float2*)(vwsm + jl);
#pragma unroll
            for (int mt = 0; mt < 2; mt++)
#pragma unroll
                for (int half = 0; half < 2; half++) {
                    const int lrow = mt * 16 + half * 8 + r;
                    float* wp = wsum + lrow * WSTRIDE + jl;
                    float2 w = *(float2*)wp;
                    float iv = inv[mt * 2 + half];
                    w.x += c[mt][nt][half * 2]     * iv * vw2.x;
                    w.y += c[mt][nt][half * 2 + 1] * iv * vw2.y;
                    *(float2*)wp = w;
                }
        }
    }
    __syncthreads();

    // dirs contraction
    const float bias = bf[0];
#pragma unroll
    for (int rr = 0; rr < 4; rr++) {
        const int ii = wid * 4 + rr;
        const float* dp = dirs + ((size_t)(b * SEQ + i0 + ii)) * SEQ * 3;
        const float* wrow = wsum + ii * WSTRIDE;
        float a0 = 0.f, a1 = 0.f, a2 = 0.f;
#pragma unroll
        for (int t = 0; t < 8; t++) {
            const int jb = (lane + t * 32) * 4;
            const float* dpe = dp + (size_t)jb * 3;
            float4 f0 = *(const float4*)(dpe);
            float4 f1 = *(const float4*)(dpe + 4);
            float4 f2 = *(const float4*)(dpe + 8);
            float4 w4 = *(const float4*)(wrow + jb);
            a0 = fmaf(f0.x, w4.x, a0); a1 = fmaf(f0.y, w4.x, a1); a2 = fmaf(f0.z, w4.x, a2);
            a0 = fmaf(f0.w, w4.y, a0); a1 = fmaf(f1.x, w4.y, a1); a2 = fmaf(f1.y, w4.y, a2);
            a0 = fmaf(f1.z, w4.z, a0); a1 = fmaf(f1.w, w4.z, a1); a2 = fmaf(f2.x, w4.z, a2);
            a0 = fmaf(f2.y, w4.w, a0); a1 = fmaf(f2.z, w4.w, a1); a2 = fmaf(f2.w, w4.w, a2);
        }
#pragma unroll
        for (int o = 16; o; o >>= 1) {
            a0 += __shfl_xor_sync(0xffffffffu, a0, o);
            a1 += __shfl_xor_sync(0xffffffffu, a1, o);
            a2 += __shfl_xor_sync(0xffffffffu, a2, o);
        }
        if (lane == 0) {
            float* op = out + ((size_t)(b * SEQ + i0 + ii)) * 3;
            op[0] = a0 + bias;
            op[1] = a1 + bias;
            op[2] = a2 + bias;
        }
    }
}

// ============================================================
extern "C" void kernel_launch(void* const* d_in, const int* in_sizes, int n_in,
                              void* d_out, int out_size)
{
    const float* emb   = (const float*)d_in[0];  // (4,1024,512)
    const float* dirs  = (const float*)d_in[1];  // (4,1024,1024,3)
    const float* dmask = (const float*)d_in[2];  // (32,1024,1024)
    const float* Wp    = (const float*)d_in[3];  // (512,1536)
    const float* bp    = (const float*)d_in[4];  // (1536,)
    const float* wf    = (const float*)d_in[5];  // (512,)
    const float* bf    = (const float*)d_in[6];  // (1,)
    float* out = (float*)d_out;                  // (4,1024,3)

    cudaFuncSetAttribute(qkv_cp, cudaFuncAttributeMaxDynamicSharedMemorySize, QKV_SMEM);
    cudaFuncSetAttribute(fused_attn, cudaFuncAttributeMaxDynamicSharedMemorySize,
                         FUSED_SMEM);

    prep_emb<<<2048, 256>>>(emb);
    prep_W<<<dim3(48, 16), 256>>>(Wp);
    qkv_cp<<<dim3(12, 32), 256, QKV_SMEM>>>(bp);
    vw_kernel<<<BATCH * NH * SEQ / 8, 256>>>(wf);
    fused_attn<<<BATCH * 32, 256, FUSED_SMEM>>>(dmask, dirs, bf, out);
}

// round 7
// speedup vs baseline: 1.9243x; 1.0378x over previous
#include <cuda_runtime.h>
#include <cuda_bf16.h>
#include <stdint.h>
#include <math.h>

#define NH     8
#define BATCH  4
#define SEQ    1024
#define DMODEL 512
#define DH     64
#define SCALEQ 0.04419417382415922f  // 1/sqrt(512)

// ---- scratch (device globals; no allocation allowed) ----
__device__ __nv_bfloat16 gAhi[4096 * 512];   // emb hi
__device__ __nv_bfloat16 gAlo[4096 * 512];   // emb lo
__device__ __nv_bfloat16 gWhi[1536 * 512];   // W^T hi  [n][k]
__device__ __nv_bfloat16 gWlo[1536 * 512];   // W^T lo
__device__ __nv_bfloat16 gQhi[BATCH * NH * SEQ * DH];
__device__ __nv_bfloat16 gQlo[BATCH * NH * SEQ * DH];
__device__ __nv_bfloat16 gKhi[BATCH * NH * SEQ * DH];
__device__ __nv_bfloat16 gKlo[BATCH * NH * SEQ * DH];
__device__ float gV[BATCH * NH * SEQ * DH];
__device__ float gVW[BATCH * NH * SEQ];

// ============================================================
// helpers
// ============================================================
__device__ __forceinline__ uint32_t smem_u32(const void* p) {
    uint32_t a;
    asm("{ .reg .u64 t; cvta.to.shared.u64 t, %1; cvt.u32.u64 %0, t; }"
        : "=r"(a) : "l"(p));
    return a;
}
__device__ __forceinline__ void split_bf16(float x, __nv_bfloat16& h, __nv_bfloat16& l) {
    h = __float2bfloat16(x);
    l = __float2bfloat16(x - __bfloat162float(h));
}
__device__ __forceinline__ uint32_t pack2(__nv_bfloat16 a, __nv_bfloat16 b) {
    __nv_bfloat162 t; t.x = a; t.y = b;
    return *(uint32_t*)&t;
}
__device__ __forceinline__ void mma_bf16(float c[4], uint32_t a0, uint32_t a1,
                                         uint32_t a2, uint32_t a3,
                                         uint32_t b0, uint32_t b1) {
    asm volatile(
        "mma.sync.aligned.m16n8k16.row.col.f32.bf16.bf16.f32 "
        "{%0,%1,%2,%3}, {%4,%5,%6,%7}, {%8,%9}, {%0,%1,%2,%3};"
        : "+f"(c[0]), "+f"(c[1]), "+f"(c[2]), "+f"(c[3])
        : "r"(a0), "r"(a1), "r"(a2), "r"(a3), "r"(b0), "r"(b1));
}
__device__ __forceinline__ void ldm_x4(uint32_t r[4], uint32_t addr) {
    asm volatile("ldmatrix.sync.aligned.m8n8.x4.shared.b16 {%0,%1,%2,%3}, [%4];"
                 : "=r"(r[0]), "=r"(r[1]), "=r"(r[2]), "=r"(r[3]) : "r"(addr));
}
__device__ __forceinline__ void cp_async16(uint32_t dst, const void* src) {
    asm volatile("cp.async.cg.shared.global [%0], [%1], 16;" :: "r"(dst), "l"(src));
}
__device__ __forceinline__ void cp_commit() {
    asm volatile("cp.async.commit_group;");
}

// ============================================================
// P1: split emb -> gAhi/gAlo
// ============================================================
__global__ __launch_bounds__(256) void prep_emb(const float* __restrict__ emb)
{
    size_t i = ((size_t)blockIdx.x * 256 + threadIdx.x) * 4;
    float4 v = *(const float4*)(emb + i);
    __nv_bfloat16 h[4], l[4];
    split_bf16(v.x, h[0], l[0]); split_bf16(v.y, h[1], l[1]);
    split_bf16(v.z, h[2], l[2]); split_bf16(v.w, h[3], l[3]);
    uint2 uh = make_uint2(pack2(h[0], h[1]), pack2(h[2], h[3]));
    uint2 ul = make_uint2(pack2(l[0], l[1]), pack2(l[2], l[3]));
    *(uint2*)(gAhi + i) = uh;
    *(uint2*)(gAlo + i) = ul;
}

// ============================================================
// P2: transpose+split W (512x1536) -> gWhi/gWlo [1536][512]
// ============================================================
__global__ __launch_bounds__(256) void prep_W(const float* __restrict__ W)
{
    __shared__ float t[32][33];
    const int n0 = blockIdx.x * 32, k0 = blockIdx.y * 32;
    const int tx = threadIdx.x & 31, ty = threadIdx.x >> 5;
#pragma unroll
    for (int it = 0; it < 4; it++)
        t[ty + it * 8][tx] = W[(size_t)(k0 + ty + it * 8) * 1536 + n0 + tx];
    __syncthreads();
#pragma unroll
    for (int it = 0; it < 4; it++) {
        int n = ty + it * 8;
        float v = t[tx][n];
        __nv_bfloat16 h, l;
        split_bf16(v, h, l);
        gWhi[(size_t)(n0 + n) * 512 + k0 + tx] = h;
        gWlo[(size_t)(n0 + n) * 512 + k0 + tx] = l;
    }
}

// ============================================================
// K1: qkv GEMM. cp.async double-buffer + ldmatrix fragments.
// 128x128 tile, BK=32, stages of {Ah,Al,Bh,Bl} 10240B each.
// ============================================================
#define TS 40
#define TILE_B  (128 * TS * 2)          // 10240
#define STAGE_B (4 * TILE_B)            // 40960
#define QKV_SMEM (2 * STAGE_B + 512)    // + bias

__global__ __launch_bounds__(256, 2) void qkv_cp(const float* __restrict__ bias)
{
    extern __shared__ char sm[];
    float* bias_sm = (float*)(sm + 2 * STAGE_B);
    const uint32_t base = smem_u32(sm);

    const int tid = threadIdx.x;
    const int wid = tid >> 5, lane = tid & 31;
    const int wM = wid & 3, wN = wid >> 2;
    const int bx = blockIdx.x, by = blockIdx.y;
    const int lr = lane & 7, lg = lane >> 3;

    if (tid < 128) bias_sm[tid] = bias[bx * 128 + tid];

    // ldmatrix per-thread byte offsets within a tile
    uint32_t offA[2], offB[4];
#pragma unroll
    for (int mt = 0; mt < 2; mt++) {
        int row = wM * 32 + mt * 16 + (lg & 1) * 8 + lr;
        offA[mt] = row * (TS * 2) + (lg >> 1) * 16;
    }
#pragma unroll
    for (int p = 0; p < 4; p++) {
        int n = wN * 64 + p * 16 + (lg >> 1) * 8 + lr;
        offB[p] = n * (TS * 2) + (lg & 1) * 16;
    }

    const __nv_bfloat16* srcs[4] = {
        gAhi + (size_t)(by * 128) * 512,
        gAlo + (size_t)(by * 128) * 512,
        gWhi + (size_t)(bx * 128) * 512,
        gWlo + (size_t)(bx * 128) * 512
    };

    float c[2][8][4];
#pragma unroll
    for (int mt = 0; mt < 2; mt++)
#pragma unroll
        for (int nt = 0; nt < 8; nt++)
#pragma unroll
            for (int j = 0; j < 4; j++) c[mt][nt][j] = 0.f;

    auto issue = [&](int ch, int s) {
        const uint32_t sb = base + s * STAGE_B;
#pragma unroll
        for (int l = 0; l < 8; l++) {
            int idx = tid + l * 256;
            int tile = idx >> 9;
            int rem = idx & 511;
            int row = rem >> 2, chunk = rem & 3;
            uint32_t dst = sb + tile * TILE_B + row * (TS * 2) + chunk * 16;
            const __nv_bfloat16* src = srcs[tile] + (size_t)row * 512 + ch * 32 + chunk * 8;
            cp_async16(dst, src);
        }
        cp_commit();
    };

    issue(0, 0);
    for (int ch = 0; ch < 16; ch++) {
        const int s = ch & 1;
        if (ch < 15) {
            issue(ch + 1, s ^ 1);
            asm volatile("cp.async.wait_group 1;");
        } else {
            asm volatile("cp.async.wait_group 0;");
        }
        __syncthreads();

        const uint32_t sb = base + s * STAGE_B;
#pragma unroll
        for (int ks = 0; ks < 2; ks++) {
            const uint32_t kofs = ks * 32;
            uint32_t ah[2][4], al[2][4];
            ldm_x4(ah[0], sb + offA[0] + kofs);
            ldm_x4(ah[1], sb + offA[1] + kofs);
            ldm_x4(al[0], sb + TILE_B + offA[0] + kofs);
            ldm_x4(al[1], sb + TILE_B + offA[1] + kofs);
#pragma unroll
            for (int p = 0; p < 4; p++) {
                uint32_t bh[4], bl[4];
                ldm_x4(bh, sb + 2 * TILE_B + offB[p] + kofs);
                ldm_x4(bl, sb + 3 * TILE_B + offB[p] + kofs);
#pragma unroll
                for (int mt = 0; mt < 2; mt++) {
                    mma_bf16(c[mt][2 * p],     ah[mt][0], ah[mt][1], ah[mt][2], ah[mt][3], bh[0], bh[1]);
                    mma_bf16(c[mt][2 * p],     ah[mt][0], ah[mt][1], ah[mt][2], ah[mt][3], bl[0], bl[1]);
                    mma_bf16(c[mt][2 * p],     al[mt][0], al[mt][1], al[mt][2], al[mt][3], bh[0], bh[1]);
                    mma_bf16(c[mt][2 * p + 1], ah[mt][0], ah[mt][1], ah[mt][2], ah[mt][3], bh[2], bh[3]);
                    mma_bf16(c[mt][2 * p + 1], ah[mt][0], ah[mt][1], ah[mt][2], ah[mt][3], bl[2], bl[3]);
                    mma_bf16(c[mt][2 * p + 1], al[mt][0], al[mt][1], al[mt][2], al[mt][3], bh[2], bh[3]);
                }
            }
        }
        __syncthreads();
    }

    // Epilogue: bias (+Q scale); Q/K stored split bf16, V fp32.
    const int r  = lane >> 2;
    const int cq = (lane & 3) * 2;
#pragma unroll
    for (int nt = 0; nt < 8; nt++) {
        const int lcol = wN * 64 + nt * 8 + cq;
        const int gcol = bx * 128 + lcol;
        const int which = gcol >> 9;
        const int idx = gcol & 511;
        const int h = idx >> 6, w = idx & 63;
        const float sc = (which == 0) ? SCALEQ : 1.0f;
        const float b0 = bias_sm[lcol], b1 = bias_sm[lcol + 1];
#pragma unroll
        for (int mt = 0; mt < 2; mt++) {
            const int grow = by * 128 + wM * 32 + mt * 16 + r;
            const int bb = grow >> 10, ii = grow & 1023;
            size_t dst = (((size_t)(bb * NH + h) * SEQ) + ii) * DH + w;
            float x0 = (c[mt][nt][0] + b0) * sc;
            float x1 = (c[mt][nt][1] + b1) * sc;
            float x2 = (c[mt][nt][2] + b0) * sc;
            float x3 = (c[mt][nt][3] + b1) * sc;
            if (which == 2) {
                *(float2*)(gV + dst) = make_float2(x0, x1);
                *(float2*)(gV + dst + (size_t)8 * DH) = make_float2(x2, x3);
            } else {
                __nv_bfloat16 h0, l0, h1, l1, h2, l2, h3, l3;
                split_bf16(x0, h0, l0); split_bf16(x1, h1, l1);
                split_bf16(x2, h2, l2); split_bf16(x3, h3, l3);
                __nv_bfloat16* ph = (which == 0) ? gQhi : gKhi;
                __nv_bfloat16* pl = (which == 0) ? gQlo : gKlo;
                *(uint32_t*)(ph + dst) = pack2(h0, h1);
                *(uint32_t*)(pl + dst) = pack2(l0, l1);
                *(uint32_t*)(ph + dst + (size_t)8 * DH) = pack2(h2, h3);
                *(uint32_t*)(pl + dst + (size_t)8 * DH) = pack2(l2, l3);
            }
        }
    }
}

// ============================================================
// K2: vw[b,h,j] = sum_w V[b,h,j,w] * w_force[h*64+w]
// ============================================================
__global__ __launch_bounds__(256) void vw_kernel(const float* __restrict__ wf)
{
    int warp = threadIdx.x >> 5;
    int lane = threadIdx.x & 31;
    int row = blockIdx.x * 8 + warp;
    int h = (row >> 10) & 7;
    const float* vrow = gV + (size_t)row * DH;
    float s = vrow[lane] * wf[h * 64 + lane] + vrow[lane + 32] * wf[h * 64 + lane + 32];
#pragma unroll
    for (int o = 16; o; o >>= 1) s += __shfl_xor_sync(0xffffffffu, s, o);
    if (lane == 0) gVW[row] = s;
}

// ============================================================
// K3 (fused): per (b, i-tile of 32): scores+softmax+vw+dirs.
// SMEM: wsum[32][1028] f32 : 0..131584
//       Qhi [32][72] bf16  : 131584..136192
//       Qlo [32][72] bf16  : 136192..140800
//       vwsm[1024] f32     : 140800..144896
//       redm[32][8]        : 144896..145920
//       redl[32][8]        : 145920..146944
// ============================================================
#define QS 72
#define WSTRIDE 1028
#define FUSED_SMEM 146944

__global__ __launch_bounds__(256, 1) void fused_attn(
    const float* __restrict__ dmask, const float* __restrict__ dirs,
    const float* __restrict__ bf, float* __restrict__ out)
{
    extern __shared__ char sm[];
    float* wsum = (float*)sm;
    __nv_bfloat16* Qhi = (__nv_bfloat16*)(sm + 131584);
    __nv_bfloat16* Qlo = (__nv_bfloat16*)(sm + 136192);
    float* vwsm = (float*)(sm + 140800);
    float* redm = (float*)(sm + 144896);
    float* redl = (float*)(sm + 145920);

    const int tid = threadIdx.x, wid = tid >> 5, lane = tid & 31;
    const int r = lane >> 2, cq = (lane & 3) * 2;
    const int lr = lane & 7, lg = lane >> 3;
    const int b = blockIdx.x >> 5;
    const int i0 = (blockIdx.x & 31) * 32;
    const int jbase = wid * 128;

    const uint32_t qhiB = smem_u32(Qhi);
    const uint32_t qloB = smem_u32(Qlo);
    uint32_t offQ[2];
#pragma unroll
    for (int mt = 0; mt < 2; mt++) {
        int row = mt * 16 + (lg & 1) * 8 + lr;
        offQ[mt] = row * (QS * 2) + (lg >> 1) * 16;
    }

    for (int idx = tid; idx < 32 * WSTRIDE; idx += 256) wsum[idx] = 0.f;

    for (int h = 0; h < NH; h++) {
        const int bh = b * NH + h;
        __syncthreads();

        // stage Q tile (already split) + vw
        {
            const __nv_bfloat16* Qhb = gQhi + ((size_t)bh * SEQ + i0) * DH;
            const __nv_bfloat16* Qlb = gQlo + ((size_t)bh * SEQ + i0) * DH;
            int row = tid >> 3, cc = tid & 7;
            *(uint4*)(Qhi + row * QS + cc * 8) = *(const uint4*)(Qhb + row * DH + cc * 8);
            *(uint4*)(Qlo + row * QS + cc * 8) = *(const uint4*)(Qlb + row * DH + cc * 8);
            float4 vv = *(const float4*)(gVW + (size_t)bh * SEQ + tid * 4);
            *(float4*)(vwsm + tid * 4) = vv;
        }
        __syncthreads();

        // S = Q @ K^T  (K bf16 fragments straight from global)
        float c[2][16][4];
#pragma unroll
        for (int mt = 0; mt < 2; mt++)
#pragma unroll
            for (int nt = 0; nt < 16; nt++)
#pragma unroll
                for (int e = 0; e < 4; e++) c[mt][nt][e] = 0.f;

        const __nv_bfloat16* Khb = gKhi + (size_t)bh * SEQ * DH;
        const __nv_bfloat16* Klb = gKlo + (size_t)bh * SEQ * DH;
#pragma unroll
        for (int ks = 0; ks < 4; ks++) {
            const int k0 = ks * 16;
            uint32_t ah[2][4], al[2][4];
            ldm_x4(ah[0], qhiB + offQ[0] + ks * 32);
            ldm_x4(ah[1], qhiB + offQ[1] + ks * 32);
            ldm_x4(al[0], qloB + offQ[0] + ks * 32);
            ldm_x4(al[1], qloB + offQ[1] + ks * 32);
#pragma unroll
            for (int nt = 0; nt < 16; nt++) {
                const int j = jbase + nt * 8 + r;
                const size_t ko = (size_t)j * DH + k0 + cq;
                uint32_t bh0 = *(const uint32_t*)(Khb + ko);
                uint32_t bh1 = *(const uint32_t*)(Khb + ko + 8);
                uint32_t bl0 = *(const uint32_t*)(Klb + ko);
                uint32_t bl1 = *(const uint32_t*)(Klb + ko + 8);
#pragma unroll
                for (int mt = 0; mt < 2; mt++) {
                    mma_bf16(c[mt][nt], ah[mt][0], ah[mt][1], ah[mt][2], ah[mt][3], bh0, bh1);
                    mma_bf16(c[mt][nt], ah[mt][0], ah[mt][1], ah[mt][2], ah[mt][3], bl0, bl1);
                    mma_bf16(c[mt][nt], al[mt][0], al[mt][1], al[mt][2], al[mt][3], bh0, bh1);
                }
            }
        }

        // add mask + row max
        float tmax[4] = {-1e30f, -1e30f, -1e30f, -1e30f};
#pragma unroll
        for (int mt = 0; mt < 2; mt++) {
#pragma unroll
            for (int half = 0; half < 2; half++) {
                const int lrow = mt * 16 + half * 8 + r;
                const size_t rowaddr = ((size_t)bh * SEQ + (i0 + lrow)) * SEQ + jbase + cq;
                float tm = -1e30f;
#pragma unroll
                for (int nt = 0; nt < 16; nt++) {
                    float2 m = *(const float2*)(dmask + rowaddr + nt * 8);
                    float x0 = c[mt][nt][half * 2]     + m.x;
                    float x1 = c[mt][nt][half * 2 + 1] + m.y;
                    c[mt][nt][half * 2]     = x0;
                    c[mt][nt][half * 2 + 1] = x1;
                    tm = fmaxf(tm, fmaxf(x0, x1));
                }
                tmax[mt * 2 + half] = tm;
            }
        }
#pragma unroll
        for (int e = 0; e < 4; e++) {
            tmax[e] = fmaxf(tmax[e], __shfl_xor_sync(0xffffffffu, tmax[e], 1));
            tmax[e] = fmaxf(tmax[e], __shfl_xor_sync(0xffffffffu, tmax[e], 2));
        }
        if ((lane & 3) == 0) {
#pragma unroll
            for (int mt = 0; mt < 2; mt++)
#pragma unroll
                for (int half = 0; half < 2; half++)
                    redm[(mt * 16 + half * 8 + r) * 8 + wid] = tmax[mt * 2 + half];
        }
        __syncthreads();

        float mf[4];
#pragma unroll
        for (int mt = 0; mt < 2; mt++)
#pragma unroll
            for (int half = 0; half < 2; half++) {
                const float* rp = redm + (mt * 16 + half * 8 + r) * 8;
                float mm = rp[0];
#pragma unroll
                for (int w = 1; w < 8; w++) mm = fmaxf(mm, rp[w]);
                mf[mt * 2 + half] = mm;
            }

        // exp + row sum
        float tsum[4] = {0.f, 0.f, 0.f, 0.f};
#pragma unroll
        for (int mt = 0; mt < 2; mt++)
#pragma unroll
            for (int nt = 0; nt < 16; nt++) {
#pragma unroll
                for (int half = 0; half < 2; half++) {
                    float p0 = __expf(c[mt][nt][half * 2]     - mf[mt * 2 + half]);
                    float p1 = __expf(c[mt][nt][half * 2 + 1] - mf[mt * 2 + half]);
                    c[mt][nt][half * 2]     = p0;
                    c[mt][nt][half * 2 + 1] = p1;
                    tsum[mt * 2 + half] += p0 + p1;
                }
            }
#pragma unroll
        for (int e = 0; e < 4; e++) {
            tsum[e] += __shfl_xor_sync(0xffffffffu, tsum[e], 1);
            tsum[e] += __shfl_xor_sync(0xffffffffu, tsum[e], 2);
        }
        if ((lane & 3) == 0) {
#pragma unroll
            for (int mt = 0; mt < 2; mt++)
#pragma unroll
                for (int half = 0; half < 2; half++)
                    redl[(mt * 16 + half * 8 + r) * 8 + wid] = tsum[mt * 2 + half];
        }
        __syncthreads();

        float inv[4];
#pragma unroll
        for (int mt = 0; mt < 2; mt++)
#pragma unroll
            for (int half = 0; half < 2; half++) {
                const float* rp = redl + (mt * 16 + half * 8 + r) * 8;
                float ss = rp[0];
#pragma unroll
                for (int w = 1; w < 8; w++) ss += rp[w];
                inv[mt * 2 + half] = 1.0f / ss;
            }

        // wsum += attn * vw
#pragma unroll
        for (int nt = 0; nt < 16; nt++) {
            const int jl = jbase + nt * 8 + cq;
            float2 vw2 = *(const float2*)(vwsm + jl);
#pragma unroll
            for (int mt = 0; mt < 2; mt++)
#pragma unroll
                for (int half = 0; half < 2; half++) {
                    const int lrow = mt * 16 + half * 8 + r;
                    float* wp = wsum + lrow * WSTRIDE + jl;
                    float2 w = *(float2*)wp;
                    float iv = inv[mt * 2 + half];
                    w.x += c[mt][nt][half * 2]     * iv * vw2.x;
                    w.y += c[mt][nt][half * 2 + 1] * iv * vw2.y;
                    *(float2*)wp = w;
                }
        }
    }
    __syncthreads();

    // dirs contraction
    const float bias = bf[0];
#pragma unroll
    for (int rr = 0; rr < 4; rr++) {
        const int ii = wid * 4 + rr;
        const float* dp = dirs + ((size_t)(b * SEQ + i0 + ii)) * SEQ * 3;
        const float* wrow = wsum + ii * WSTRIDE;
        float a0 = 0.f, a1 = 0.f, a2 = 0.f;
#pragma unroll
        for (int t = 0; t < 8; t++) {
            const int jb = (lane + t * 32) * 4;
            const float* dpe = dp + (size_t)jb * 3;
            float4 f0 = *(const float4*)(dpe);
            float4 f1 = *(const float4*)(dpe + 4);
            float4 f2 = *(const float4*)(dpe + 8);
            float4 w4 = *(const float4*)(wrow + jb);
            a0 = fmaf(f0.x, w4.x, a0); a1 = fmaf(f0.y, w4.x, a1); a2 = fmaf(f0.z, w4.x, a2);
            a0 = fmaf(f0.w, w4.y, a0); a1 = fmaf(f1.x, w4.y, a1); a2 = fmaf(f1.y, w4.y, a2);
            a0 = fmaf(f1.z, w4.z, a0); a1 = fmaf(f1.w, w4.z, a1); a2 = fmaf(f2.x, w4.z, a2);
            a0 = fmaf(f2.y, w4.w, a0); a1 = fmaf(f2.z, w4.w, a1); a2 = fmaf(f2.w, w4.w, a2);
        }
#pragma unroll
        for (int o = 16; o; o >>= 1) {
            a0 += __shfl_xor_sync(0xffffffffu, a0, o);
            a1 += __shfl_xor_sync(0xffffffffu, a1, o);
            a2 += __shfl_xor_sync(0xffffffffu, a2, o);
        }
        if (lane == 0) {
            float* op = out + ((size_t)(b * SEQ + i0 + ii)) * 3;
            op[0] = a0 + bias;
            op[1] = a1 + bias;
            op[2] = a2 + bias;
        }
    }
}

// ============================================================
extern "C" void kernel_launch(void* const* d_in, const int* in_sizes, int n_in,
                              void* d_out, int out_size)
{
    const float* emb   = (const float*)d_in[0];  // (4,1024,512)
    const float* dirs  = (const float*)d_in[1];  // (4,1024,1024,3)
    const float* dmask = (const float*)d_in[2];  // (32,1024,1024)
    const float* Wp    = (const float*)d_in[3];  // (512,1536)
    const float* bp    = (const float*)d_in[4];  // (1536,)
    const float* wf    = (const float*)d_in[5];  // (512,)
    const float* bf    = (const float*)d_in[6];  // (1,)
    float* out = (float*)d_out;                  // (4,1024,3)

    cudaFuncSetAttribute(qkv_cp, cudaFuncAttributeMaxDynamicSharedMemorySize, QKV_SMEM);
    cudaFuncSetAttribute(fused_attn, cudaFuncAttributeMaxDynamicSharedMemorySize,
                         FUSED_SMEM);

    prep_emb<<<2048, 256>>>(emb);
    prep_W<<<dim3(48, 16), 256>>>(Wp);
    qkv_cp<<<dim3(12, 32), 256, QKV_SMEM>>>(bp);
    vw_kernel<<<BATCH * NH * SEQ / 8, 256>>>(wf);
    fused_attn<<<BATCH * 32, 256, FUSED_SMEM>>>(dmask, dirs, bf, out);
}